// round 13
// baseline (speedup 1.0000x reference)
#include <cuda_runtime.h>
#include <cuda_bf16.h>
#include <cuda_fp16.h>
#include <math.h>
#include <stdint.h>

#define NROWS 8192
#define DIM   1024
#define THR   0.85f

// Scratch (allocation-free: __device__ globals)
__device__ float g_h[(size_t)NROWS * DIM];              // 32 MB: h-fp16 | enc-fp16
__device__ __nv_bfloat16 g_hi[(size_t)NROWS * DIM];     // 16 MB (act fp16)
__device__ __nv_bfloat16 g_wt[(size_t)2 * DIM * DIM];   // 4 MB (Wt1, Wt2 fp16)

// ===========================================================================
// sm_80-generic PTX helpers (base sm_103 target: no tcgen05)
// ===========================================================================
__device__ __forceinline__ uint32_t smem_u32(const void* p) {
    uint32_t a;
    asm("{ .reg .u64 t; cvta.to.shared.u64 t, %1; cvt.u32.u64 %0, t; }"
        : "=r"(a) : "l"(p));
    return a;
}
__device__ __forceinline__ void cp16(uint32_t dst, const void* src) {
    asm volatile("cp.async.cg.shared.global [%0], [%1], 16;"
                 :: "r"(dst), "l"(src));
}
__device__ __forceinline__ void ldsm_x4(uint32_t* r, uint32_t addr) {
    asm volatile("ldmatrix.sync.aligned.m8n8.x4.shared.b16 {%0,%1,%2,%3}, [%4];"
                 : "=r"(r[0]), "=r"(r[1]), "=r"(r[2]), "=r"(r[3]) : "r"(addr));
}
__device__ __forceinline__ void mma_f16(float* c, const uint32_t* a,
                                        const uint32_t* b) {
    asm volatile("mma.sync.aligned.m16n8k16.row.col.f32.f16.f16.f32 "
                 "{%0,%1,%2,%3}, {%4,%5,%6,%7}, {%8,%9}, {%0,%1,%2,%3};"
                 : "+f"(c[0]), "+f"(c[1]), "+f"(c[2]), "+f"(c[3])
                 : "r"(a[0]), "r"(a[1]), "r"(a[2]), "r"(a[3]),
                   "r"(b[0]), "r"(b[1]));
}

// smem tile: 128 rows x 128B (64 fp16, BK=64). chunk(16B) swizzle c^(row&7):
// 8 consecutive rows at fixed chunk cover all 8 slots -> conflict-free LDSM.
__device__ __forceinline__ uint32_t swz128(uint32_t row, uint32_t chunk) {
    return row * 128u + ((chunk ^ (row & 7u)) * 16u);
}

// Load one phase (chunk base cb) of fragments: A 64 rows, B 64 cols.
#define LOAD_FRAGS(A, B, uA_, uB_, cb)                                        \
    do {                                                                      \
        _Pragma("unroll")                                                     \
        for (int mt = 0; mt < 4; mt++)                                        \
            ldsm_x4((A)[mt], (uA_) + swz128(arow0 + mt * 16, (cb) + achb));   \
        _Pragma("unroll")                                                     \
        for (int p = 0; p < 4; p++) {                                         \
            uint32_t r_[4];                                                   \
            ldsm_x4(r_, (uB_) + swz128(brow0 + p * 16, (cb) + bchb));         \
            (B)[p * 2][0] = r_[0]; (B)[p * 2][1] = r_[1];                     \
            (B)[p * 2 + 1][0] = r_[2]; (B)[p * 2 + 1][1] = r_[3];             \
        }                                                                     \
    } while (0)

#define MMA_ALL(A, B)                                                         \
    do {                                                                      \
        _Pragma("unroll")                                                     \
        for (int mt = 0; mt < 4; mt++)                                        \
            _Pragma("unroll")                                                 \
            for (int nt = 0; nt < 8; nt++)                                    \
                mma_f16(acc[mt][nt], (A)[mt], (B)[nt]);                       \
    } while (0)

// Mainloop core shared by both GEMMs: 16 iterations of BK=64, 3-stage ring,
// ONE wait_group+barrier per iteration; refill targets the stage read last
// iteration (top barrier proves all its readers are done); empty commits on
// tail iterations keep wait_group accounting exact.
#define GEMM_MAINLOOP()                                                       \
    load_stage(0, 0);                                                         \
    asm volatile("cp.async.commit_group;");                                   \
    load_stage(1, 1);                                                         \
    asm volatile("cp.async.commit_group;");                                   \
    load_stage(2, 2);                                                         \
    asm volatile("cp.async.commit_group;");                                   \
    for (int it = 0; it < 16; it++) {                                         \
        asm volatile("cp.async.wait_group 1;");                               \
        __syncthreads();                                                      \
        const int st = it % 3;                                                \
        const uint32_t uA = sb + (uint32_t)st * 32768u;                       \
        const uint32_t uB = uA + 16384u;                                      \
        if (it >= 1 && it + 2 < 16) load_stage((it + 2) % 3, it + 2);         \
        asm volatile("cp.async.commit_group;");                               \
        uint32_t af[4][4], bf[8][2];                                          \
        _Pragma("unroll")                                                     \
        for (int ks = 0; ks < 4; ks++) {                                      \
            LOAD_FRAGS(af, bf, uA, uB, (uint32_t)(ks * 2));                   \
            MMA_ALL(af, bf);                                                  \
        }                                                                     \
    }

// ===========================================================================
// Encoder GEMM: fp16 1-pass, 128x128 tile, 4 warps (64x64 warp tile).
// ===========================================================================
template <typename OutT>
__global__ __launch_bounds__(128, 2) void gemm_enc(
    const __half* __restrict__ A, const __half* __restrict__ B,
    OutT* __restrict__ C, int ldc, const float* __restrict__ bias) {
    extern __shared__ char sm[];
    const uint32_t sb = smem_u32(sm);

    const int rowBase = blockIdx.y * 128;
    const int colBase = blockIdx.x * 128;

    const int tid = threadIdx.x;
    const int wid = tid >> 5;
    const int lane = tid & 31;
    const int wm = (wid & 1) * 64;
    const int wn = (wid >> 1) * 64;

    const char* gA = (const char*)A + (size_t)rowBase * 2048;
    const char* gB = (const char*)B + (size_t)colBase * 2048;

    auto load_stage = [&](int st_, int kb) {
        const char* bases[2] = {gA, gB};
#pragma unroll
        for (int t = 0; t < 2; t++) {
#pragma unroll
            for (int h = 0; h < 8; h++) {
                const int c = tid + h * 128;
                const uint32_t row = (uint32_t)(c >> 3), kch = (uint32_t)(c & 7);
                const uint32_t dst = sb + (uint32_t)st_ * 32768u +
                                     (uint32_t)t * 16384u + swz128(row, kch);
                cp16(dst, bases[t] + (size_t)row * 2048 + (size_t)kb * 128 + kch * 16);
            }
        }
    };

    float acc[4][8][4];
#pragma unroll
    for (int i = 0; i < 4; i++)
#pragma unroll
        for (int j = 0; j < 8; j++)
#pragma unroll
            for (int k = 0; k < 4; k++) acc[i][j][k] = 0.f;

    const uint32_t arow0 = (uint32_t)(wm + (lane & 15));
    const uint32_t achb = (uint32_t)(lane >> 4);
    const uint32_t brow0 = (uint32_t)(wn + (lane & 7) + ((lane & 16) >> 1));
    const uint32_t bchb = (uint32_t)((lane >> 3) & 1);

    GEMM_MAINLOOP()

    const int g = lane >> 2, tg = lane & 3;
#pragma unroll
    for (int mt = 0; mt < 4; mt++)
#pragma unroll
        for (int nt = 0; nt < 8; nt++) {
            const int c0 = colBase + wn + nt * 8 + tg * 2;
            const float bx = bias[c0], by = bias[c0 + 1];
#pragma unroll
            for (int hf = 0; hf < 2; hf++) {
                const int r = rowBase + wm + mt * 16 + g + hf * 8;
                const float vx = acc[mt][nt][hf * 2 + 0] + bx;
                const float vy = acc[mt][nt][hf * 2 + 1] + by;
                if (sizeof(OutT) == 2) {
                    __half2 hv;
                    hv.x = __float2half(vx); hv.y = __float2half(vy);
                    *(__half2*)&C[(size_t)r * ldc + c0] = hv;
                } else {
                    float2 v; v.x = vx; v.y = vy;
                    *(float2*)&C[(size_t)r * ldc + c0] = v;
                }
            }
        }
}

// ===========================================================================
// Sim GEMM: fp16 1-pass, lower-tri 128x128 tiles, same BK=64 mainloop.
// Epilogue: direct coalesced fragment store (+dup); smem-staged mirror.
// ===========================================================================
__global__ __launch_bounds__(128, 2) void sim_tc_kernel(
    const __half* __restrict__ E,
    float* __restrict__ out, float* __restrict__ dup) {
    extern __shared__ char sm[];
    const uint32_t sb = smem_u32(sm);

    const int b = blockIdx.x;
    int bi = (int)((sqrtf(8.f * b + 1.f) - 1.f) * 0.5f);
    while ((bi + 1) * (bi + 2) / 2 <= b) bi++;
    while (bi * (bi + 1) / 2 > b) bi--;
    const int bj = b - bi * (bi + 1) / 2;
    const int rowBase = bi * 128;
    const int colBase = bj * 128;
    const bool diag = (rowBase == colBase);

    const int tid = threadIdx.x;
    const int wid = tid >> 5;
    const int lane = tid & 31;
    const int wm = (wid & 1) * 64;
    const int wn = (wid >> 1) * 64;

    const char* gA = (const char*)E + (size_t)rowBase * 2048;
    const char* gB = (const char*)E + (size_t)colBase * 2048;

    auto load_stage = [&](int st_, int kb) {
        const char* bases[2] = {gA, gB};
#pragma unroll
        for (int t = 0; t < 2; t++) {
#pragma unroll
            for (int h = 0; h < 8; h++) {
                const int c = tid + h * 128;
                const uint32_t row = (uint32_t)(c >> 3), kch = (uint32_t)(c & 7);
                const uint32_t dst = sb + (uint32_t)st_ * 32768u +
                                     (uint32_t)t * 16384u + swz128(row, kch);
                cp16(dst, bases[t] + (size_t)row * 2048 + (size_t)kb * 128 + kch * 16);
            }
        }
    };

    float acc[4][8][4];
#pragma unroll
    for (int i = 0; i < 4; i++)
#pragma unroll
        for (int j = 0; j < 8; j++)
#pragma unroll
            for (int k = 0; k < 4; k++) acc[i][j][k] = 0.f;

    const uint32_t arow0 = (uint32_t)(wm + (lane & 15));
    const uint32_t achb = (uint32_t)(lane >> 4);
    const uint32_t brow0 = (uint32_t)(wn + (lane & 7) + ((lane & 16) >> 1));
    const uint32_t bchb = (uint32_t)((lane >> 3) & 1);

    GEMM_MAINLOOP()

    // ---- epilogue part 1: direct coalesced stores of out[r][c] + dup ----
    const int g = lane >> 2, tg = lane & 3;
#pragma unroll
    for (int mt = 0; mt < 4; mt++)
#pragma unroll
        for (int nt = 0; nt < 8; nt++) {
            const int c0 = colBase + wn + nt * 8 + tg * 2;
#pragma unroll
            for (int hf = 0; hf < 2; hf++) {
                const int r = rowBase + wm + mt * 16 + g + hf * 8;
                const float vx = acc[mt][nt][hf * 2 + 0];
                const float vy = acc[mt][nt][hf * 2 + 1];
                if (!diag) {
                    float2 v; v.x = vx; v.y = vy;
                    *(float2*)&out[(size_t)r * NROWS + c0] = v;
                    if (dup) {
                        if (vx > THR) dup[r] = 1.0f;
                        if (vy > THR) dup[r] = 1.0f;
                    }
                } else {
                    if (r >= c0) {
                        out[(size_t)r * NROWS + c0] = vx;
                        if (dup && r > c0 && vx > THR) dup[r] = 1.0f;
                    }
                    if (r >= c0 + 1) {
                        out[(size_t)r * NROWS + c0 + 1] = vy;
                        if (dup && r > c0 + 1 && vy > THR) dup[r] = 1.0f;
                    }
                }
            }
        }

    // ---- epilogue part 2: smem-staged transposed mirror ----
    asm volatile("cp.async.wait_group 0;");
    __syncthreads();
    float* tile = (float*)sm;  // [128][129] reuses pipeline smem
#pragma unroll
    for (int mt = 0; mt < 4; mt++)
#pragma unroll
        for (int nt = 0; nt < 8; nt++) {
            const int cl = wn + nt * 8 + tg * 2;
#pragma unroll
            for (int hf = 0; hf < 2; hf++) {
                const int rl = wm + mt * 16 + g + hf * 8;
                tile[rl * 129 + cl] = acc[mt][nt][hf * 2 + 0];
                tile[rl * 129 + cl + 1] = acc[mt][nt][hf * 2 + 1];
            }
        }
    __syncthreads();
    for (int it = tid; it < 16384; it += 128) {
        const int c = it >> 7, r = it & 127;
        if (!diag || r > c)
            out[(size_t)(colBase + c) * NROWS + rowBase + r] = tile[r * 129 + c];
    }
}

// ===========================================================================
// prep: split S -> fp16 (blocks 0..8191) and transpose+convert W1/W2
// ===========================================================================
__global__ __launch_bounds__(256) void prep_kernel(
    const float* __restrict__ S, const float* __restrict__ W1,
    const float* __restrict__ W2, __half* __restrict__ act,
    __half* __restrict__ wt1, __half* __restrict__ wt2) {
    const int b = blockIdx.x;
    const int tid = threadIdx.x;
    if (b < 8192) {
        const size_t i = (size_t)b * 256 + tid;
        float4 x = ((const float4*)S)[i];
        __half2 hp0, hp1;
        hp0.x = __float2half(x.x); hp0.y = __float2half(x.y);
        hp1.x = __float2half(x.z); hp1.y = __float2half(x.w);
        uint2 hv;
        hv.x = *(uint32_t*)&hp0; hv.y = *(uint32_t*)&hp1;
        ((uint2*)act)[i] = hv;
    } else {
        const int b2 = b - 8192;
        const float* W = (b2 < 1024) ? W1 : W2;
        __half* Wt = (b2 < 1024) ? wt1 : wt2;
        const int b3 = b2 & 1023;
        const int n0 = (b3 & 31) * 32, k0 = (b3 >> 5) * 32;
        __shared__ float t[32][33];
        const int x = tid & 31, ty = tid >> 5;
#pragma unroll
        for (int yy = ty; yy < 32; yy += 8)
            t[yy][x] = W[(size_t)(k0 + yy) * DIM + n0 + x];
        __syncthreads();
#pragma unroll
        for (int yy = ty; yy < 32; yy += 8)
            Wt[(size_t)(n0 + yy) * DIM + k0 + x] = __float2half(t[x][yy]);
    }
}

// ===========================================================================
// LayerNorm + exact GELU: fp16 in (h), fp16 out
// ===========================================================================
__global__ __launch_bounds__(256) void ln_gelu_h_kernel(
    const __half* __restrict__ h, const float* __restrict__ gamma,
    const float* __restrict__ beta, __half* __restrict__ hi) {
    const int row = blockIdx.x;
    const int t = threadIdx.x;

    uint2 raw = ((const uint2*)(h + (size_t)row * DIM))[t];
    __half2 p0 = *(__half2*)&raw.x;
    __half2 p1 = *(__half2*)&raw.y;
    float x0 = __half2float(p0.x), x1 = __half2float(p0.y);
    float x2 = __half2float(p1.x), x3 = __half2float(p1.y);

    float s1 = x0 + x1 + x2 + x3;
    float s2 = x0 * x0 + x1 * x1 + x2 * x2 + x3 * x3;
#pragma unroll
    for (int o = 16; o > 0; o >>= 1) {
        s1 += __shfl_xor_sync(0xffffffffu, s1, o);
        s2 += __shfl_xor_sync(0xffffffffu, s2, o);
    }
    __shared__ float r1[8], r2[8];
    if ((t & 31) == 0) { r1[t >> 5] = s1; r2[t >> 5] = s2; }
    __syncthreads();
    if (t < 32) {
        s1 = (t < 8) ? r1[t] : 0.f;
        s2 = (t < 8) ? r2[t] : 0.f;
#pragma unroll
        for (int o = 4; o > 0; o >>= 1) {
            s1 += __shfl_xor_sync(0xffffffffu, s1, o);
            s2 += __shfl_xor_sync(0xffffffffu, s2, o);
        }
        if (t == 0) { r1[0] = s1; r2[0] = s2; }
    }
    __syncthreads();
    const float mu = r1[0] * (1.f / DIM);
    const float var = r2[0] * (1.f / DIM) - mu * mu;
    const float rstd = rsqrtf(var + 1e-5f);

    const float4 g = *(const float4*)&gamma[t * 4];
    const float4 bb = *(const float4*)&beta[t * 4];
    float y[4] = { (x0 - mu) * rstd * g.x + bb.x,
                   (x1 - mu) * rstd * g.y + bb.y,
                   (x2 - mu) * rstd * g.z + bb.z,
                   (x3 - mu) * rstd * g.w + bb.w };
    float v[4];
#pragma unroll
    for (int i = 0; i < 4; i++)
        v[i] = 0.5f * y[i] * (1.f + erff(y[i] * 0.70710678118654752f));

    __half2 hp0, hp1;
    hp0.x = __float2half(v[0]); hp0.y = __float2half(v[1]);
    hp1.x = __float2half(v[2]); hp1.y = __float2half(v[3]);
    uint2 hv;
    hv.x = *(uint32_t*)&hp0; hv.y = *(uint32_t*)&hp1;
    ((uint2*)hi)[(size_t)row * (DIM / 4) + t] = hv;
}

// ===========================================================================
// Row L2 normalize IN PLACE on fp16 enc; also zeroes dup[row]
// ===========================================================================
__global__ __launch_bounds__(256) void l2norm_f16_inplace_kernel(
    __half* __restrict__ e, float* __restrict__ dup) {
    const int row = blockIdx.x;
    const int t = threadIdx.x;

    uint2 raw = ((uint2*)(e + (size_t)row * DIM))[t];
    __half2 p0 = *(__half2*)&raw.x;
    __half2 p1 = *(__half2*)&raw.y;
    float x0 = __half2float(p0.x), x1 = __half2float(p0.y);
    float x2 = __half2float(p1.x), x3 = __half2float(p1.y);

    float s2 = x0 * x0 + x1 * x1 + x2 * x2 + x3 * x3;
#pragma unroll
    for (int o = 16; o > 0; o >>= 1) s2 += __shfl_xor_sync(0xffffffffu, s2, o);
    __shared__ float r2[8];
    if ((t & 31) == 0) r2[t >> 5] = s2;
    __syncthreads();
    if (t < 32) {
        s2 = (t < 8) ? r2[t] : 0.f;
#pragma unroll
        for (int o = 4; o > 0; o >>= 1) s2 += __shfl_xor_sync(0xffffffffu, s2, o);
        if (t == 0) r2[0] = s2;
    }
    __syncthreads();
    const float inv = 1.f / fmaxf(sqrtf(r2[0]), 1e-12f);

    __half2 hp0, hp1;
    hp0.x = __float2half(x0 * inv); hp0.y = __float2half(x1 * inv);
    hp1.x = __float2half(x2 * inv); hp1.y = __float2half(x3 * inv);
    uint2 hv;
    hv.x = *(uint32_t*)&hp0; hv.y = *(uint32_t*)&hp1;
    ((uint2*)(e + (size_t)row * DIM))[t] = hv;
    if (dup && t == 0) dup[row] = 0.0f;
}

// ===========================================================================
extern "C" void kernel_launch(void* const* d_in, const int* in_sizes, int n_in,
                              void* d_out, int out_size) {
    const float* S     = (const float*)d_in[0];
    const float* W1    = (const float*)d_in[1];
    const float* b1    = (const float*)d_in[2];
    const float* gamma = (const float*)d_in[3];
    const float* beta  = (const float*)d_in[4];
    const float* W2    = (const float*)d_in[5];
    const float* b2    = (const float*)d_in[6];
    float* out = (float*)d_out;

    float* hbuf;
    __nv_bfloat16 *hib, *wtb;
    cudaGetSymbolAddress((void**)&hbuf, g_h);
    cudaGetSymbolAddress((void**)&hib, g_hi);
    cudaGetSymbolAddress((void**)&wtb, g_wt);
    __half* act = (__half*)hib;
    __half* wt1 = (__half*)wtb;
    __half* wt2 = wt1 + (size_t)DIM * DIM;
    __half* hh  = (__half*)hbuf;
    __half* eh  = hh + (size_t)NROWS * DIM;

    const int GEMM_SMEM = 3 * 32768;     // 96 KB
    const int SIM_SMEM = 3 * 32768;      // 96 KB (epilogue tile 66KB reuses it)
    cudaFuncSetAttribute(gemm_enc<__half>,
                         cudaFuncAttributeMaxDynamicSharedMemorySize, GEMM_SMEM);
    cudaFuncSetAttribute(sim_tc_kernel,
                         cudaFuncAttributeMaxDynamicSharedMemorySize, SIM_SMEM);

    float* dup = nullptr;
    if (out_size >= NROWS * NROWS + NROWS) dup = out + (size_t)NROWS * NROWS;

    // 1) prep: S -> fp16; W1, W2 -> Wt fp16 (single launch)
    prep_kernel<<<8192 + 2048, 256>>>(S, W1, W2, act, wt1, wt2);
    // 2) h = S @ W1 + b1  (fp16 1-pass, fp16 output)
    gemm_enc<__half><<<dim3(DIM / 128, NROWS / 128), 128, GEMM_SMEM>>>(
        act, wt1, hh, DIM, b1);
    // 3) LayerNorm + GELU (fp16 in/out)
    ln_gelu_h_kernel<<<NROWS, 256>>>(hh, gamma, beta, act);
    // 4) enc = gelu(ln(h)) @ W2 + b2  (fp16 1-pass, fp16 output)
    gemm_enc<__half><<<dim3(DIM / 128, NROWS / 128), 128, GEMM_SMEM>>>(
        act, wt2, eh, DIM, b2);
    // 5) L2 normalize in place on fp16 enc (+ zero dup)
    l2norm_f16_inplace_kernel<<<NROWS, 256>>>(eh, dup);
    // 6) sim lower-tri fp16 1-pass; direct store + staged mirror + dup
    const int NT = NROWS / 128;
    sim_tc_kernel<<<NT * (NT + 1) / 2, 128, SIM_SMEM>>>(eh, out, dup);
}

// round 14
// speedup vs baseline: 1.0466x; 1.0466x over previous
#include <cuda_runtime.h>
#include <cuda_bf16.h>
#include <cuda_fp16.h>
#include <math.h>
#include <stdint.h>

#define NROWS 8192
#define DIM   1024
#define THR   0.85f

// Scratch (allocation-free: __device__ globals)
__device__ float g_h[(size_t)NROWS * DIM];              // 32 MB: h-fp16 | enc-fp16
__device__ __nv_bfloat16 g_hi[(size_t)NROWS * DIM];     // 16 MB (act fp16)
__device__ __nv_bfloat16 g_wt[(size_t)2 * DIM * DIM];   // 4 MB (Wt1, Wt2 fp16)
__device__ float g_invn[NROWS];                         // 32 KB (1/||enc_r||)

// ===========================================================================
// sm_80-generic PTX helpers (base sm_103 target: no tcgen05)
// ===========================================================================
__device__ __forceinline__ uint32_t smem_u32(const void* p) {
    uint32_t a;
    asm("{ .reg .u64 t; cvta.to.shared.u64 t, %1; cvt.u32.u64 %0, t; }"
        : "=r"(a) : "l"(p));
    return a;
}
__device__ __forceinline__ void cp16(uint32_t dst, const void* src) {
    asm volatile("cp.async.cg.shared.global [%0], [%1], 16;"
                 :: "r"(dst), "l"(src));
}
__device__ __forceinline__ void ldsm_x4(uint32_t* r, uint32_t addr) {
    asm volatile("ldmatrix.sync.aligned.m8n8.x4.shared.b16 {%0,%1,%2,%3}, [%4];"
                 : "=r"(r[0]), "=r"(r[1]), "=r"(r[2]), "=r"(r[3]) : "r"(addr));
}
__device__ __forceinline__ void mma_f16(float* c, const uint32_t* a,
                                        const uint32_t* b) {
    asm volatile("mma.sync.aligned.m16n8k16.row.col.f32.f16.f16.f32 "
                 "{%0,%1,%2,%3}, {%4,%5,%6,%7}, {%8,%9}, {%0,%1,%2,%3};"
                 : "+f"(c[0]), "+f"(c[1]), "+f"(c[2]), "+f"(c[3])
                 : "r"(a[0]), "r"(a[1]), "r"(a[2]), "r"(a[3]),
                   "r"(b[0]), "r"(b[1]));
}

// smem tile: 128 rows x 64B. 16B-chunk swizzle, conflict-free LDSM phases.
__device__ __forceinline__ uint32_t swz(uint32_t row, uint32_t chunk) {
    uint32_t c = chunk ^ (row & 3u) ^ ((row >> 2) & 1u);
    return row * 64u + c * 16u;
}

// Load one phase of fragments (A 64 rows, B 64 cols) from a stage.
#define LOAD_FRAGS(A, B, uA_, uB_, ksoff)                                   \
    do {                                                                    \
        _Pragma("unroll")                                                   \
        for (int mt = 0; mt < 4; mt++)                                      \
            ldsm_x4((A)[mt], (uA_) + swz(arow0 + mt * 16, (ksoff) + achb)); \
        _Pragma("unroll")                                                   \
        for (int p = 0; p < 4; p++) {                                       \
            uint32_t r_[4];                                                 \
            ldsm_x4(r_, (uB_) + swz(brow0 + p * 16, (ksoff) + bchb));       \
            (B)[p * 2][0] = r_[0]; (B)[p * 2][1] = r_[1];                   \
            (B)[p * 2 + 1][0] = r_[2]; (B)[p * 2 + 1][1] = r_[3];           \
        }                                                                   \
    } while (0)

#define MMA_ALL(A, B)                                                       \
    do {                                                                    \
        _Pragma("unroll")                                                   \
        for (int mt = 0; mt < 4; mt++)                                      \
            _Pragma("unroll")                                               \
            for (int nt = 0; nt < 8; nt++)                                  \
                mma_f16(acc[mt][nt], (A)[mt], (B)[nt]);                     \
    } while (0)

// Round-12 proven mainloop: BK=32, 4 stages, reg-double-buffered frags.
#define GEMM_MAINLOOP()                                                     \
    load_stage(0, 0);                                                       \
    asm volatile("cp.async.commit_group;");                                 \
    load_stage(1, 1);                                                       \
    asm volatile("cp.async.commit_group;");                                 \
    load_stage(2, 2);                                                       \
    asm volatile("cp.async.commit_group;");                                 \
    asm volatile("cp.async.wait_group 1;");                                 \
    __syncthreads();                                                        \
    LOAD_FRAGS(a0, b0, sb, sb + 8192u, 0u);                                 \
    int st = 0;                                                             \
    for (int kc = 0; kc < 32; kc++) {                                       \
        const uint32_t uA = sb + st * 16384u;                               \
        const uint32_t uB = uA + 8192u;                                     \
        LOAD_FRAGS(a1, b1, uA, uB, 2u);                                     \
        MMA_ALL(a0, b0);                                                    \
        if (kc + 1 < 32) {                                                  \
            const uint32_t uA2 = sb + ((st + 1) & 3) * 16384u;              \
            LOAD_FRAGS(a0, b0, uA2, uA2 + 8192u, 0u);                       \
        }                                                                   \
        if (kc + 3 < 32) load_stage((st + 3) & 3, kc + 3);                  \
        asm volatile("cp.async.commit_group;");                             \
        MMA_ALL(a1, b1);                                                    \
        asm volatile("cp.async.wait_group 1;");                             \
        __syncthreads();                                                    \
        st = (st + 1) & 3;                                                  \
    }

// ===========================================================================
// Encoder GEMM: fp16 1-pass, 128x128 tile, 4 warps (64x64 warp tile),
// 4-stage cp.async, register-double-buffered fragments. (round-12 proven)
// ===========================================================================
template <typename OutT>
__global__ __launch_bounds__(128, 2) void gemm_enc(
    const __half* __restrict__ A, const __half* __restrict__ B,
    OutT* __restrict__ C, int ldc, const float* __restrict__ bias) {
    extern __shared__ char sm[];
    const uint32_t sb = smem_u32(sm);

    const int rowBase = blockIdx.y * 128;
    const int colBase = blockIdx.x * 128;

    const int tid = threadIdx.x;
    const int wid = tid >> 5;
    const int lane = tid & 31;
    const int wm = (wid & 1) * 64;
    const int wn = (wid >> 1) * 64;

    const char* gA = (const char*)A + (size_t)rowBase * 2048;
    const char* gB = (const char*)B + (size_t)colBase * 2048;

    auto load_stage = [&](int st_, int kc_) {
        const char* bases[2] = {gA, gB};
#pragma unroll
        for (int t = 0; t < 2; t++) {
#pragma unroll
            for (int h = 0; h < 4; h++) {
                const int c = tid + h * 128;
                const uint32_t row = c >> 2, kch = c & 3;
                const uint32_t dst = sb + st_ * 16384u + t * 8192u + swz(row, kch);
                cp16(dst, bases[t] + (size_t)row * 2048 + (size_t)kc_ * 64 + kch * 16);
            }
        }
    };

    float acc[4][8][4];
#pragma unroll
    for (int i = 0; i < 4; i++)
#pragma unroll
        for (int j = 0; j < 8; j++)
#pragma unroll
            for (int k = 0; k < 4; k++) acc[i][j][k] = 0.f;

    const uint32_t arow0 = (uint32_t)(wm + (lane & 15));
    const uint32_t achb = (uint32_t)(lane >> 4);
    const uint32_t brow0 = (uint32_t)(wn + (lane & 7) + ((lane & 16) >> 1));
    const uint32_t bchb = (uint32_t)((lane >> 3) & 1);

    uint32_t a0[4][4], b0[8][2], a1[4][4], b1[8][2];

    GEMM_MAINLOOP()

    const int g = lane >> 2, tg = lane & 3;
#pragma unroll
    for (int mt = 0; mt < 4; mt++)
#pragma unroll
        for (int nt = 0; nt < 8; nt++) {
            const int c0 = colBase + wn + nt * 8 + tg * 2;
            const float bx = bias[c0], by = bias[c0 + 1];
#pragma unroll
            for (int hf = 0; hf < 2; hf++) {
                const int r = rowBase + wm + mt * 16 + g + hf * 8;
                const float vx = acc[mt][nt][hf * 2 + 0] + bx;
                const float vy = acc[mt][nt][hf * 2 + 1] + by;
                if (sizeof(OutT) == 2) {
                    __half2 hv;
                    hv.x = __float2half(vx); hv.y = __float2half(vy);
                    *(__half2*)&C[(size_t)r * ldc + c0] = hv;
                } else {
                    float2 v; v.x = vx; v.y = vy;
                    *(float2*)&C[(size_t)r * ldc + c0] = v;
                }
            }
        }
}

// ===========================================================================
// Sim GEMM: fp16 1-pass on UNNORMALIZED enc; epilogue scales by
// invn[r]*invn[c] (fused L2 normalization), then direct store (+dup) and
// smem-staged transposed mirror. (round-12 proven skeleton)
// ===========================================================================
__global__ __launch_bounds__(128, 2) void sim_tc_kernel(
    const __half* __restrict__ E, const float* __restrict__ invn,
    float* __restrict__ out, float* __restrict__ dup) {
    extern __shared__ char sm[];
    const uint32_t sb = smem_u32(sm);

    const int b = blockIdx.x;
    int bi = (int)((sqrtf(8.f * b + 1.f) - 1.f) * 0.5f);
    while ((bi + 1) * (bi + 2) / 2 <= b) bi++;
    while (bi * (bi + 1) / 2 > b) bi--;
    const int bj = b - bi * (bi + 1) / 2;
    const int rowBase = bi * 128;
    const int colBase = bj * 128;
    const bool diag = (rowBase == colBase);

    const int tid = threadIdx.x;
    const int wid = tid >> 5;
    const int lane = tid & 31;
    const int wm = (wid & 1) * 64;
    const int wn = (wid >> 1) * 64;

    const char* gA = (const char*)E + (size_t)rowBase * 2048;
    const char* gB = (const char*)E + (size_t)colBase * 2048;

    auto load_stage = [&](int st_, int kc_) {
        const char* bases[2] = {gA, gB};
#pragma unroll
        for (int t = 0; t < 2; t++) {
#pragma unroll
            for (int h = 0; h < 4; h++) {
                const int c = tid + h * 128;
                const uint32_t row = c >> 2, kch = c & 3;
                const uint32_t dst = sb + st_ * 16384u + t * 8192u + swz(row, kch);
                cp16(dst, bases[t] + (size_t)row * 2048 + (size_t)kc_ * 64 + kch * 16);
            }
        }
    };

    float acc[4][8][4];
#pragma unroll
    for (int i = 0; i < 4; i++)
#pragma unroll
        for (int j = 0; j < 8; j++)
#pragma unroll
            for (int k = 0; k < 4; k++) acc[i][j][k] = 0.f;

    const uint32_t arow0 = (uint32_t)(wm + (lane & 15));
    const uint32_t achb = (uint32_t)(lane >> 4);
    const uint32_t brow0 = (uint32_t)(wn + (lane & 7) + ((lane & 16) >> 1));
    const uint32_t bchb = (uint32_t)((lane >> 3) & 1);

    uint32_t a0[4][4], b0[8][2], a1[4][4], b1[8][2];

    GEMM_MAINLOOP()

    // ---- fused normalization: acc[r][c] *= invn[r] * invn[c] ----
    const int g = lane >> 2, tg = lane & 3;
    float rn[4][2], cn[8][2];
#pragma unroll
    for (int mt = 0; mt < 4; mt++) {
        rn[mt][0] = invn[rowBase + wm + mt * 16 + g];
        rn[mt][1] = invn[rowBase + wm + mt * 16 + g + 8];
    }
#pragma unroll
    for (int nt = 0; nt < 8; nt++) {
        const int c0 = colBase + wn + nt * 8 + tg * 2;
        cn[nt][0] = invn[c0];
        cn[nt][1] = invn[c0 + 1];
    }
#pragma unroll
    for (int mt = 0; mt < 4; mt++)
#pragma unroll
        for (int nt = 0; nt < 8; nt++) {
            acc[mt][nt][0] *= rn[mt][0] * cn[nt][0];
            acc[mt][nt][1] *= rn[mt][0] * cn[nt][1];
            acc[mt][nt][2] *= rn[mt][1] * cn[nt][0];
            acc[mt][nt][3] *= rn[mt][1] * cn[nt][1];
        }

    // ---- epilogue part 1: direct coalesced stores of out[r][c] + dup ----
#pragma unroll
    for (int mt = 0; mt < 4; mt++)
#pragma unroll
        for (int nt = 0; nt < 8; nt++) {
            const int c0 = colBase + wn + nt * 8 + tg * 2;
#pragma unroll
            for (int hf = 0; hf < 2; hf++) {
                const int r = rowBase + wm + mt * 16 + g + hf * 8;
                const float vx = acc[mt][nt][hf * 2 + 0];
                const float vy = acc[mt][nt][hf * 2 + 1];
                if (!diag) {
                    float2 v; v.x = vx; v.y = vy;
                    *(float2*)&out[(size_t)r * NROWS + c0] = v;
                    if (dup) {
                        if (vx > THR) dup[r] = 1.0f;
                        if (vy > THR) dup[r] = 1.0f;
                    }
                } else {
                    if (r >= c0) {
                        out[(size_t)r * NROWS + c0] = vx;
                        if (dup && r > c0 && vx > THR) dup[r] = 1.0f;
                    }
                    if (r >= c0 + 1) {
                        out[(size_t)r * NROWS + c0 + 1] = vy;
                        if (dup && r > c0 + 1 && vy > THR) dup[r] = 1.0f;
                    }
                }
            }
        }

    // ---- epilogue part 2: smem-staged transposed mirror ----
    asm volatile("cp.async.wait_group 0;");
    __syncthreads();
    float* tile = (float*)sm;  // [128][129]
#pragma unroll
    for (int mt = 0; mt < 4; mt++)
#pragma unroll
        for (int nt = 0; nt < 8; nt++) {
            const int cl = wn + nt * 8 + tg * 2;
#pragma unroll
            for (int hf = 0; hf < 2; hf++) {
                const int rl = wm + mt * 16 + g + hf * 8;
                tile[rl * 129 + cl] = acc[mt][nt][hf * 2 + 0];
                tile[rl * 129 + cl + 1] = acc[mt][nt][hf * 2 + 1];
            }
        }
    __syncthreads();
    for (int it = tid; it < 16384; it += 128) {
        const int c = it >> 7, r = it & 127;
        if (!diag || r > c)
            out[(size_t)(colBase + c) * NROWS + rowBase + r] = tile[r * 129 + c];
    }
}

// ===========================================================================
// prep: split S -> fp16 (blocks 0..8191) and transpose+convert W1/W2
// ===========================================================================
__global__ __launch_bounds__(256) void prep_kernel(
    const float* __restrict__ S, const float* __restrict__ W1,
    const float* __restrict__ W2, __half* __restrict__ act,
    __half* __restrict__ wt1, __half* __restrict__ wt2) {
    const int b = blockIdx.x;
    const int tid = threadIdx.x;
    if (b < 8192) {
        const size_t i = (size_t)b * 256 + tid;
        float4 x = ((const float4*)S)[i];
        __half2 hp0, hp1;
        hp0.x = __float2half(x.x); hp0.y = __float2half(x.y);
        hp1.x = __float2half(x.z); hp1.y = __float2half(x.w);
        uint2 hv;
        hv.x = *(uint32_t*)&hp0; hv.y = *(uint32_t*)&hp1;
        ((uint2*)act)[i] = hv;
    } else {
        const int b2 = b - 8192;
        const float* W = (b2 < 1024) ? W1 : W2;
        __half* Wt = (b2 < 1024) ? wt1 : wt2;
        const int b3 = b2 & 1023;
        const int n0 = (b3 & 31) * 32, k0 = (b3 >> 5) * 32;
        __shared__ float t[32][33];
        const int x = tid & 31, ty = tid >> 5;
#pragma unroll
        for (int yy = ty; yy < 32; yy += 8)
            t[yy][x] = W[(size_t)(k0 + yy) * DIM + n0 + x];
        __syncthreads();
#pragma unroll
        for (int yy = ty; yy < 32; yy += 8)
            Wt[(size_t)(n0 + yy) * DIM + k0 + x] = __float2half(t[x][yy]);
    }
}

// ===========================================================================
// LayerNorm + exact GELU: fp16 in (h), fp16 out
// ===========================================================================
__global__ __launch_bounds__(256) void ln_gelu_h_kernel(
    const __half* __restrict__ h, const float* __restrict__ gamma,
    const float* __restrict__ beta, __half* __restrict__ hi) {
    const int row = blockIdx.x;
    const int t = threadIdx.x;

    uint2 raw = ((const uint2*)(h + (size_t)row * DIM))[t];
    __half2 p0 = *(__half2*)&raw.x;
    __half2 p1 = *(__half2*)&raw.y;
    float x0 = __half2float(p0.x), x1 = __half2float(p0.y);
    float x2 = __half2float(p1.x), x3 = __half2float(p1.y);

    float s1 = x0 + x1 + x2 + x3;
    float s2 = x0 * x0 + x1 * x1 + x2 * x2 + x3 * x3;
#pragma unroll
    for (int o = 16; o > 0; o >>= 1) {
        s1 += __shfl_xor_sync(0xffffffffu, s1, o);
        s2 += __shfl_xor_sync(0xffffffffu, s2, o);
    }
    __shared__ float r1[8], r2[8];
    if ((t & 31) == 0) { r1[t >> 5] = s1; r2[t >> 5] = s2; }
    __syncthreads();
    if (t < 32) {
        s1 = (t < 8) ? r1[t] : 0.f;
        s2 = (t < 8) ? r2[t] : 0.f;
#pragma unroll
        for (int o = 4; o > 0; o >>= 1) {
            s1 += __shfl_xor_sync(0xffffffffu, s1, o);
            s2 += __shfl_xor_sync(0xffffffffu, s2, o);
        }
        if (t == 0) { r1[0] = s1; r2[0] = s2; }
    }
    __syncthreads();
    const float mu = r1[0] * (1.f / DIM);
    const float var = r2[0] * (1.f / DIM) - mu * mu;
    const float rstd = rsqrtf(var + 1e-5f);

    const float4 g = *(const float4*)&gamma[t * 4];
    const float4 bb = *(const float4*)&beta[t * 4];
    float y[4] = { (x0 - mu) * rstd * g.x + bb.x,
                   (x1 - mu) * rstd * g.y + bb.y,
                   (x2 - mu) * rstd * g.z + bb.z,
                   (x3 - mu) * rstd * g.w + bb.w };
    float v[4];
#pragma unroll
    for (int i = 0; i < 4; i++)
        v[i] = 0.5f * y[i] * (1.f + erff(y[i] * 0.70710678118654752f));

    __half2 hp0, hp1;
    hp0.x = __float2half(v[0]); hp0.y = __float2half(v[1]);
    hp1.x = __float2half(v[2]); hp1.y = __float2half(v[3]);
    uint2 hv;
    hv.x = *(uint32_t*)&hp0; hv.y = *(uint32_t*)&hp1;
    ((uint2*)hi)[(size_t)row * (DIM / 4) + t] = hv;
}

// ===========================================================================
// Row norm: invn[row] = 1/max(||enc_row||, 1e-12) from fp16 enc (read-only);
// also zeroes dup[row].
// ===========================================================================
__global__ __launch_bounds__(256) void rownorm_kernel(
    const __half* __restrict__ e, float* __restrict__ invn,
    float* __restrict__ dup) {
    const int row = blockIdx.x;
    const int t = threadIdx.x;

    uint2 raw = ((const uint2*)(e + (size_t)row * DIM))[t];
    __half2 p0 = *(__half2*)&raw.x;
    __half2 p1 = *(__half2*)&raw.y;
    float x0 = __half2float(p0.x), x1 = __half2float(p0.y);
    float x2 = __half2float(p1.x), x3 = __half2float(p1.y);

    float s2 = x0 * x0 + x1 * x1 + x2 * x2 + x3 * x3;
#pragma unroll
    for (int o = 16; o > 0; o >>= 1) s2 += __shfl_xor_sync(0xffffffffu, s2, o);
    __shared__ float r2[8];
    if ((t & 31) == 0) r2[t >> 5] = s2;
    __syncthreads();
    if (t == 0) {
        float s = 0.f;
#pragma unroll
        for (int i = 0; i < 8; i++) s += r2[i];
        invn[row] = 1.f / fmaxf(sqrtf(s), 1e-12f);
        if (dup) dup[row] = 0.0f;
    }
}

// ===========================================================================
extern "C" void kernel_launch(void* const* d_in, const int* in_sizes, int n_in,
                              void* d_out, int out_size) {
    const float* S     = (const float*)d_in[0];
    const float* W1    = (const float*)d_in[1];
    const float* b1    = (const float*)d_in[2];
    const float* gamma = (const float*)d_in[3];
    const float* beta  = (const float*)d_in[4];
    const float* W2    = (const float*)d_in[5];
    const float* b2    = (const float*)d_in[6];
    float* out = (float*)d_out;

    float* hbuf;
    __nv_bfloat16 *hib, *wtb;
    float* invn;
    cudaGetSymbolAddress((void**)&hbuf, g_h);
    cudaGetSymbolAddress((void**)&hib, g_hi);
    cudaGetSymbolAddress((void**)&wtb, g_wt);
    cudaGetSymbolAddress((void**)&invn, g_invn);
    __half* act = (__half*)hib;
    __half* wt1 = (__half*)wtb;
    __half* wt2 = wt1 + (size_t)DIM * DIM;
    __half* hh  = (__half*)hbuf;
    __half* eh  = hh + (size_t)NROWS * DIM;

    const int GEMM_SMEM = 4 * 16384;     // 64 KB
    const int SIM_SMEM = 128 * 129 * 4;  // 66048 B (>= 4*16384 pipeline)
    cudaFuncSetAttribute(gemm_enc<__half>,
                         cudaFuncAttributeMaxDynamicSharedMemorySize, GEMM_SMEM);
    cudaFuncSetAttribute(sim_tc_kernel,
                         cudaFuncAttributeMaxDynamicSharedMemorySize, SIM_SMEM);

    float* dup = nullptr;
    if (out_size >= NROWS * NROWS + NROWS) dup = out + (size_t)NROWS * NROWS;

    // 1) prep: S -> fp16; W1, W2 -> Wt fp16 (single launch)
    prep_kernel<<<8192 + 2048, 256>>>(S, W1, W2, act, wt1, wt2);
    // 2) h = S @ W1 + b1  (fp16 1-pass, fp16 output)
    gemm_enc<__half><<<dim3(DIM / 128, NROWS / 128), 128, GEMM_SMEM>>>(
        act, wt1, hh, DIM, b1);
    // 3) LayerNorm + GELU (fp16 in/out)
    ln_gelu_h_kernel<<<NROWS, 256>>>(hh, gamma, beta, act);
    // 4) enc = gelu(ln(h)) @ W2 + b2  (fp16 1-pass, fp16 output, UNNORMALIZED)
    gemm_enc<__half><<<dim3(DIM / 128, NROWS / 128), 128, GEMM_SMEM>>>(
        act, wt2, eh, DIM, b2);
    // 5) row norms (read-only 16MB) + zero dup
    rownorm_kernel<<<NROWS, 256>>>(eh, invn, dup);
    // 6) sim lower-tri fp16 1-pass; normalization fused into epilogue
    const int NT = NROWS / 128;
    sim_tc_kernel<<<NT * (NT + 1) / 2, 128, SIM_SMEM>>>(eh, invn, out, dup);
}

// round 15
// speedup vs baseline: 1.0552x; 1.0082x over previous
#include <cuda_runtime.h>
#include <cuda_bf16.h>
#include <cuda_fp16.h>
#include <math.h>
#include <stdint.h>

#define NROWS 8192
#define DIM   1024
#define THR   0.85f

// Scratch (allocation-free: __device__ globals)
__device__ float g_h[(size_t)NROWS * DIM];              // 32 MB: h-fp16 | enc-fp16
__device__ __nv_bfloat16 g_hi[(size_t)NROWS * DIM];     // 16 MB (act fp16)
__device__ __nv_bfloat16 g_wt[(size_t)2 * DIM * DIM];   // 4 MB (Wt1, Wt2 fp16)
__device__ float g_partial[8 * NROWS];                  // 256 KB (per-colblock ||.||^2)

// ===========================================================================
// sm_80-generic PTX helpers (base sm_103 target: no tcgen05)
// ===========================================================================
__device__ __forceinline__ uint32_t smem_u32(const void* p) {
    uint32_t a;
    asm("{ .reg .u64 t; cvta.to.shared.u64 t, %1; cvt.u32.u64 %0, t; }"
        : "=r"(a) : "l"(p));
    return a;
}
__device__ __forceinline__ void cp16(uint32_t dst, const void* src) {
    asm volatile("cp.async.cg.shared.global [%0], [%1], 16;"
                 :: "r"(dst), "l"(src));
}
__device__ __forceinline__ void ldsm_x4(uint32_t* r, uint32_t addr) {
    asm volatile("ldmatrix.sync.aligned.m8n8.x4.shared.b16 {%0,%1,%2,%3}, [%4];"
                 : "=r"(r[0]), "=r"(r[1]), "=r"(r[2]), "=r"(r[3]) : "r"(addr));
}
__device__ __forceinline__ void mma_f16(float* c, const uint32_t* a,
                                        const uint32_t* b) {
    asm volatile("mma.sync.aligned.m16n8k16.row.col.f32.f16.f16.f32 "
                 "{%0,%1,%2,%3}, {%4,%5,%6,%7}, {%8,%9}, {%0,%1,%2,%3};"
                 : "+f"(c[0]), "+f"(c[1]), "+f"(c[2]), "+f"(c[3])
                 : "r"(a[0]), "r"(a[1]), "r"(a[2]), "r"(a[3]),
                   "r"(b[0]), "r"(b[1]));
}

// smem tile: 128 rows x 64B. 16B-chunk swizzle, conflict-free LDSM phases.
__device__ __forceinline__ uint32_t swz(uint32_t row, uint32_t chunk) {
    uint32_t c = chunk ^ (row & 3u) ^ ((row >> 2) & 1u);
    return row * 64u + c * 16u;
}

// Load one phase of fragments (A 64 rows, B 64 cols) from a stage.
#define LOAD_FRAGS(A, B, uA_, uB_, ksoff)                                   \
    do {                                                                    \
        _Pragma("unroll")                                                   \
        for (int mt = 0; mt < 4; mt++)                                      \
            ldsm_x4((A)[mt], (uA_) + swz(arow0 + mt * 16, (ksoff) + achb)); \
        _Pragma("unroll")                                                   \
        for (int p = 0; p < 4; p++) {                                       \
            uint32_t r_[4];                                                 \
            ldsm_x4(r_, (uB_) + swz(brow0 + p * 16, (ksoff) + bchb));       \
            (B)[p * 2][0] = r_[0]; (B)[p * 2][1] = r_[1];                   \
            (B)[p * 2 + 1][0] = r_[2]; (B)[p * 2 + 1][1] = r_[3];           \
        }                                                                   \
    } while (0)

#define MMA_ALL(A, B)                                                       \
    do {                                                                    \
        _Pragma("unroll")                                                   \
        for (int mt = 0; mt < 4; mt++)                                      \
            _Pragma("unroll")                                               \
            for (int nt = 0; nt < 8; nt++)                                  \
                mma_f16(acc[mt][nt], (A)[mt], (B)[nt]);                     \
    } while (0)

// Round-12 proven mainloop: BK=32, 4 stages, reg-double-buffered frags.
#define GEMM_MAINLOOP()                                                     \
    load_stage(0, 0);                                                       \
    asm volatile("cp.async.commit_group;");                                 \
    load_stage(1, 1);                                                       \
    asm volatile("cp.async.commit_group;");                                 \
    load_stage(2, 2);                                                       \
    asm volatile("cp.async.commit_group;");                                 \
    asm volatile("cp.async.wait_group 1;");                                 \
    __syncthreads();                                                        \
    LOAD_FRAGS(a0, b0, sb, sb + 8192u, 0u);                                 \
    int st = 0;                                                             \
    for (int kc = 0; kc < 32; kc++) {                                       \
        const uint32_t uA = sb + st * 16384u;                               \
        const uint32_t uB = uA + 8192u;                                     \
        LOAD_FRAGS(a1, b1, uA, uB, 2u);                                     \
        MMA_ALL(a0, b0);                                                    \
        if (kc + 1 < 32) {                                                  \
            const uint32_t uA2 = sb + ((st + 1) & 3) * 16384u;              \
            LOAD_FRAGS(a0, b0, uA2, uA2 + 8192u, 0u);                       \
        }                                                                   \
        if (kc + 3 < 32) load_stage((st + 3) & 3, kc + 3);                  \
        asm volatile("cp.async.commit_group;");                             \
        MMA_ALL(a1, b1);                                                    \
        asm volatile("cp.async.wait_group 1;");                             \
        __syncthreads();                                                    \
        st = (st + 1) & 3;                                                  \
    }

// ===========================================================================
// Encoder GEMM: fp16 1-pass, 128x128 tile, 4 warps (64x64 warp tile),
// 4-stage cp.async, reg-double-buffered fragments. If nsum != nullptr,
// epilogue also accumulates per-row sum-of-squares of the fp16-rounded
// outputs into nsum[blockIdx.x * NROWS + r] (exactly 2 atomic contributors
// per address -> commutative -> deterministic).
// ===========================================================================
__global__ __launch_bounds__(128, 2) void gemm_enc(
    const __half* __restrict__ A, const __half* __restrict__ B,
    __half* __restrict__ C, int ldc, const float* __restrict__ bias,
    float* __restrict__ nsum) {
    extern __shared__ char sm[];
    const uint32_t sb = smem_u32(sm);

    const int rowBase = blockIdx.y * 128;
    const int colBase = blockIdx.x * 128;

    const int tid = threadIdx.x;
    const int wid = tid >> 5;
    const int lane = tid & 31;
    const int wm = (wid & 1) * 64;
    const int wn = (wid >> 1) * 64;

    const char* gA = (const char*)A + (size_t)rowBase * 2048;
    const char* gB = (const char*)B + (size_t)colBase * 2048;

    auto load_stage = [&](int st_, int kc_) {
        const char* bases[2] = {gA, gB};
#pragma unroll
        for (int t = 0; t < 2; t++) {
#pragma unroll
            for (int h = 0; h < 4; h++) {
                const int c = tid + h * 128;
                const uint32_t row = c >> 2, kch = c & 3;
                const uint32_t dst = sb + st_ * 16384u + t * 8192u + swz(row, kch);
                cp16(dst, bases[t] + (size_t)row * 2048 + (size_t)kc_ * 64 + kch * 16);
            }
        }
    };

    float acc[4][8][4];
#pragma unroll
    for (int i = 0; i < 4; i++)
#pragma unroll
        for (int j = 0; j < 8; j++)
#pragma unroll
            for (int k = 0; k < 4; k++) acc[i][j][k] = 0.f;

    const uint32_t arow0 = (uint32_t)(wm + (lane & 15));
    const uint32_t achb = (uint32_t)(lane >> 4);
    const uint32_t brow0 = (uint32_t)(wn + (lane & 7) + ((lane & 16) >> 1));
    const uint32_t bchb = (uint32_t)((lane >> 3) & 1);

    uint32_t a0[4][4], b0[8][2], a1[4][4], b1[8][2];

    GEMM_MAINLOOP()

    const int g = lane >> 2, tg = lane & 3;
    float rowsum[4][2];
#pragma unroll
    for (int i = 0; i < 4; i++) { rowsum[i][0] = 0.f; rowsum[i][1] = 0.f; }

#pragma unroll
    for (int mt = 0; mt < 4; mt++)
#pragma unroll
        for (int nt = 0; nt < 8; nt++) {
            const int c0 = colBase + wn + nt * 8 + tg * 2;
            const float bx = bias[c0], by = bias[c0 + 1];
#pragma unroll
            for (int hf = 0; hf < 2; hf++) {
                const int r = rowBase + wm + mt * 16 + g + hf * 8;
                const float vx = acc[mt][nt][hf * 2 + 0] + bx;
                const float vy = acc[mt][nt][hf * 2 + 1] + by;
                __half2 hv;
                hv.x = __float2half(vx); hv.y = __float2half(vy);
                *(__half2*)&C[(size_t)r * ldc + c0] = hv;
                if (nsum) {
                    const float px = __half2float(hv.x);
                    const float py = __half2float(hv.y);
                    rowsum[mt][hf] += px * px + py * py;
                }
            }
        }

    if (nsum) {
#pragma unroll
        for (int mt = 0; mt < 4; mt++)
#pragma unroll
            for (int hf = 0; hf < 2; hf++) {
                float s = rowsum[mt][hf];
                s += __shfl_xor_sync(0xffffffffu, s, 1);
                s += __shfl_xor_sync(0xffffffffu, s, 2);
                if (tg == 0) {
                    const int r = rowBase + wm + mt * 16 + g + hf * 8;
                    atomicAdd(&nsum[blockIdx.x * NROWS + r], s);
                }
            }
    }
}

// ===========================================================================
// Sim GEMM: fp16 1-pass on UNNORMALIZED enc; epilogue builds rsqrt(norm^2)
// tables from the per-colblock partials (fixed-order sum -> deterministic),
// scales acc, then direct store (+dup) and smem-staged transposed mirror.
// ===========================================================================
__global__ __launch_bounds__(128, 2) void sim_tc_kernel(
    const __half* __restrict__ E, const float* __restrict__ nsum,
    float* __restrict__ out, float* __restrict__ dup) {
    extern __shared__ char sm[];
    const uint32_t sb = smem_u32(sm);

    const int b = blockIdx.x;
    int bi = (int)((sqrtf(8.f * b + 1.f) - 1.f) * 0.5f);
    while ((bi + 1) * (bi + 2) / 2 <= b) bi++;
    while (bi * (bi + 1) / 2 > b) bi--;
    const int bj = b - bi * (bi + 1) / 2;
    const int rowBase = bi * 128;
    const int colBase = bj * 128;
    const bool diag = (rowBase == colBase);

    const int tid = threadIdx.x;
    const int wid = tid >> 5;
    const int lane = tid & 31;
    const int wm = (wid & 1) * 64;
    const int wn = (wid >> 1) * 64;

    const char* gA = (const char*)E + (size_t)rowBase * 2048;
    const char* gB = (const char*)E + (size_t)colBase * 2048;

    auto load_stage = [&](int st_, int kc_) {
        const char* bases[2] = {gA, gB};
#pragma unroll
        for (int t = 0; t < 2; t++) {
#pragma unroll
            for (int h = 0; h < 4; h++) {
                const int c = tid + h * 128;
                const uint32_t row = c >> 2, kch = c & 3;
                const uint32_t dst = sb + st_ * 16384u + t * 8192u + swz(row, kch);
                cp16(dst, bases[t] + (size_t)row * 2048 + (size_t)kc_ * 64 + kch * 16);
            }
        }
    };

    float acc[4][8][4];
#pragma unroll
    for (int i = 0; i < 4; i++)
#pragma unroll
        for (int j = 0; j < 8; j++)
#pragma unroll
            for (int k = 0; k < 4; k++) acc[i][j][k] = 0.f;

    const uint32_t arow0 = (uint32_t)(wm + (lane & 15));
    const uint32_t achb = (uint32_t)(lane >> 4);
    const uint32_t brow0 = (uint32_t)(wn + (lane & 7) + ((lane & 16) >> 1));
    const uint32_t bchb = (uint32_t)((lane >> 3) & 1);

    uint32_t a0[4][4], b0[8][2], a1[4][4], b1[8][2];

    GEMM_MAINLOOP()

    // ---- build inv-norm tables (1 KB smem, above the 66048B mirror tile) ----
    float* rns = (float*)(sm + 66048);   // [128]
    float* cns = rns + 128;              // [128]
    {
        float s = 0.f;
#pragma unroll
        for (int p = 0; p < 8; p++) s += nsum[p * NROWS + rowBase + tid];
        rns[tid] = rsqrtf(fmaxf(s, 1e-24f));
        float s2 = 0.f;
#pragma unroll
        for (int p = 0; p < 8; p++) s2 += nsum[p * NROWS + colBase + tid];
        cns[tid] = rsqrtf(fmaxf(s2, 1e-24f));
    }
    __syncthreads();

    const int g = lane >> 2, tg = lane & 3;
    float rn[4][2], cn[8][2];
#pragma unroll
    for (int mt = 0; mt < 4; mt++) {
        rn[mt][0] = rns[wm + mt * 16 + g];
        rn[mt][1] = rns[wm + mt * 16 + g + 8];
    }
#pragma unroll
    for (int nt = 0; nt < 8; nt++) {
        const int cl = wn + nt * 8 + tg * 2;
        cn[nt][0] = cns[cl];
        cn[nt][1] = cns[cl + 1];
    }
#pragma unroll
    for (int mt = 0; mt < 4; mt++)
#pragma unroll
        for (int nt = 0; nt < 8; nt++) {
            acc[mt][nt][0] *= rn[mt][0] * cn[nt][0];
            acc[mt][nt][1] *= rn[mt][0] * cn[nt][1];
            acc[mt][nt][2] *= rn[mt][1] * cn[nt][0];
            acc[mt][nt][3] *= rn[mt][1] * cn[nt][1];
        }

    // ---- epilogue part 1: direct coalesced stores of out[r][c] + dup ----
#pragma unroll
    for (int mt = 0; mt < 4; mt++)
#pragma unroll
        for (int nt = 0; nt < 8; nt++) {
            const int c0 = colBase + wn + nt * 8 + tg * 2;
#pragma unroll
            for (int hf = 0; hf < 2; hf++) {
                const int r = rowBase + wm + mt * 16 + g + hf * 8;
                const float vx = acc[mt][nt][hf * 2 + 0];
                const float vy = acc[mt][nt][hf * 2 + 1];
                if (!diag) {
                    float2 v; v.x = vx; v.y = vy;
                    *(float2*)&out[(size_t)r * NROWS + c0] = v;
                    if (dup) {
                        if (vx > THR) dup[r] = 1.0f;
                        if (vy > THR) dup[r] = 1.0f;
                    }
                } else {
                    if (r >= c0) {
                        out[(size_t)r * NROWS + c0] = vx;
                        if (dup && r > c0 && vx > THR) dup[r] = 1.0f;
                    }
                    if (r >= c0 + 1) {
                        out[(size_t)r * NROWS + c0 + 1] = vy;
                        if (dup && r > c0 + 1 && vy > THR) dup[r] = 1.0f;
                    }
                }
            }
        }

    // ---- epilogue part 2: smem-staged transposed mirror ----
    asm volatile("cp.async.wait_group 0;");
    __syncthreads();
    float* tile = (float*)sm;  // [128][129]
#pragma unroll
    for (int mt = 0; mt < 4; mt++)
#pragma unroll
        for (int nt = 0; nt < 8; nt++) {
            const int cl = wn + nt * 8 + tg * 2;
#pragma unroll
            for (int hf = 0; hf < 2; hf++) {
                const int rl = wm + mt * 16 + g + hf * 8;
                tile[rl * 129 + cl] = acc[mt][nt][hf * 2 + 0];
                tile[rl * 129 + cl + 1] = acc[mt][nt][hf * 2 + 1];
            }
        }
    __syncthreads();
    for (int it = tid; it < 16384; it += 128) {
        const int c = it >> 7, r = it & 127;
        if (!diag || r > c)
            out[(size_t)(colBase + c) * NROWS + rowBase + r] = tile[r * 129 + c];
    }
}

// ===========================================================================
// prep: split S -> fp16 (blocks 0..8191); transpose+convert W1/W2 (2048);
// zero nsum partials (64); zero dup (8).
// ===========================================================================
__global__ __launch_bounds__(256) void prep_kernel(
    const float* __restrict__ S, const float* __restrict__ W1,
    const float* __restrict__ W2, __half* __restrict__ act,
    __half* __restrict__ wt1, __half* __restrict__ wt2,
    float* __restrict__ nsum, float* __restrict__ dup) {
    const int b = blockIdx.x;
    const int tid = threadIdx.x;
    if (b < 8192) {
        const size_t i = (size_t)b * 256 + tid;
        float4 x = ((const float4*)S)[i];
        __half2 hp0, hp1;
        hp0.x = __float2half(x.x); hp0.y = __float2half(x.y);
        hp1.x = __float2half(x.z); hp1.y = __float2half(x.w);
        uint2 hv;
        hv.x = *(uint32_t*)&hp0; hv.y = *(uint32_t*)&hp1;
        ((uint2*)act)[i] = hv;
    } else if (b < 8192 + 2048) {
        const int b2 = b - 8192;
        const float* W = (b2 < 1024) ? W1 : W2;
        __half* Wt = (b2 < 1024) ? wt1 : wt2;
        const int b3 = b2 & 1023;
        const int n0 = (b3 & 31) * 32, k0 = (b3 >> 5) * 32;
        __shared__ float t[32][33];
        const int x = tid & 31, ty = tid >> 5;
#pragma unroll
        for (int yy = ty; yy < 32; yy += 8)
            t[yy][x] = W[(size_t)(k0 + yy) * DIM + n0 + x];
        __syncthreads();
#pragma unroll
        for (int yy = ty; yy < 32; yy += 8)
            Wt[(size_t)(n0 + yy) * DIM + k0 + x] = __float2half(t[x][yy]);
    } else if (b < 8192 + 2048 + 64) {
        const int b4 = b - (8192 + 2048);
        float4 z; z.x = 0.f; z.y = 0.f; z.z = 0.f; z.w = 0.f;
        ((float4*)nsum)[(size_t)b4 * 256 + tid] = z;
    } else {
        if (dup) {
            const int b5 = b - (8192 + 2048 + 64);
            float4 z; z.x = 0.f; z.y = 0.f; z.z = 0.f; z.w = 0.f;
            ((float4*)dup)[(size_t)b5 * 256 + tid] = z;
        }
    }
}

// ===========================================================================
// LayerNorm + exact GELU: fp16 in (h), fp16 out
// ===========================================================================
__global__ __launch_bounds__(256) void ln_gelu_h_kernel(
    const __half* __restrict__ h, const float* __restrict__ gamma,
    const float* __restrict__ beta, __half* __restrict__ hi) {
    const int row = blockIdx.x;
    const int t = threadIdx.x;

    uint2 raw = ((const uint2*)(h + (size_t)row * DIM))[t];
    __half2 p0 = *(__half2*)&raw.x;
    __half2 p1 = *(__half2*)&raw.y;
    float x0 = __half2float(p0.x), x1 = __half2float(p0.y);
    float x2 = __half2float(p1.x), x3 = __half2float(p1.y);

    float s1 = x0 + x1 + x2 + x3;
    float s2 = x0 * x0 + x1 * x1 + x2 * x2 + x3 * x3;
#pragma unroll
    for (int o = 16; o > 0; o >>= 1) {
        s1 += __shfl_xor_sync(0xffffffffu, s1, o);
        s2 += __shfl_xor_sync(0xffffffffu, s2, o);
    }
    __shared__ float r1[8], r2[8];
    if ((t & 31) == 0) { r1[t >> 5] = s1; r2[t >> 5] = s2; }
    __syncthreads();
    if (t < 32) {
        s1 = (t < 8) ? r1[t] : 0.f;
        s2 = (t < 8) ? r2[t] : 0.f;
#pragma unroll
        for (int o = 4; o > 0; o >>= 1) {
            s1 += __shfl_xor_sync(0xffffffffu, s1, o);
            s2 += __shfl_xor_sync(0xffffffffu, s2, o);
        }
        if (t == 0) { r1[0] = s1; r2[0] = s2; }
    }
    __syncthreads();
    const float mu = r1[0] * (1.f / DIM);
    const float var = r2[0] * (1.f / DIM) - mu * mu;
    const float rstd = rsqrtf(var + 1e-5f);

    const float4 g = *(const float4*)&gamma[t * 4];
    const float4 bb = *(const float4*)&beta[t * 4];
    float y[4] = { (x0 - mu) * rstd * g.x + bb.x,
                   (x1 - mu) * rstd * g.y + bb.y,
                   (x2 - mu) * rstd * g.z + bb.z,
                   (x3 - mu) * rstd * g.w + bb.w };
    float v[4];
#pragma unroll
    for (int i = 0; i < 4; i++)
        v[i] = 0.5f * y[i] * (1.f + erff(y[i] * 0.70710678118654752f));

    __half2 hp0, hp1;
    hp0.x = __float2half(v[0]); hp0.y = __float2half(v[1]);
    hp1.x = __float2half(v[2]); hp1.y = __float2half(v[3]);
    uint2 hv;
    hv.x = *(uint32_t*)&hp0; hv.y = *(uint32_t*)&hp1;
    ((uint2*)hi)[(size_t)row * (DIM / 4) + t] = hv;
}

// ===========================================================================
extern "C" void kernel_launch(void* const* d_in, const int* in_sizes, int n_in,
                              void* d_out, int out_size) {
    const float* S     = (const float*)d_in[0];
    const float* W1    = (const float*)d_in[1];
    const float* b1    = (const float*)d_in[2];
    const float* gamma = (const float*)d_in[3];
    const float* beta  = (const float*)d_in[4];
    const float* W2    = (const float*)d_in[5];
    const float* b2    = (const float*)d_in[6];
    float* out = (float*)d_out;

    float* hbuf;
    __nv_bfloat16 *hib, *wtb;
    float* nsum;
    cudaGetSymbolAddress((void**)&hbuf, g_h);
    cudaGetSymbolAddress((void**)&hib, g_hi);
    cudaGetSymbolAddress((void**)&wtb, g_wt);
    cudaGetSymbolAddress((void**)&nsum, g_partial);
    __half* act = (__half*)hib;
    __half* wt1 = (__half*)wtb;
    __half* wt2 = wt1 + (size_t)DIM * DIM;
    __half* hh  = (__half*)hbuf;
    __half* eh  = hh + (size_t)NROWS * DIM;

    const int GEMM_SMEM = 4 * 16384;           // 64 KB
    const int SIM_SMEM = 128 * 129 * 4 + 1024; // 67072 B (pipeline + norm tables)
    cudaFuncSetAttribute(gemm_enc,
                         cudaFuncAttributeMaxDynamicSharedMemorySize, GEMM_SMEM);
    cudaFuncSetAttribute(sim_tc_kernel,
                         cudaFuncAttributeMaxDynamicSharedMemorySize, SIM_SMEM);

    float* dup = nullptr;
    if (out_size >= NROWS * NROWS + NROWS) dup = out + (size_t)NROWS * NROWS;

    // 1) prep: S -> fp16; W1, W2 -> Wt fp16; zero nsum + dup (single launch)
    prep_kernel<<<8192 + 2048 + 64 + 8, 256>>>(S, W1, W2, act, wt1, wt2,
                                               nsum, dup);
    // 2) h = S @ W1 + b1  (fp16 1-pass, fp16 output, no norm accumulation)
    gemm_enc<<<dim3(DIM / 128, NROWS / 128), 128, GEMM_SMEM>>>(
        act, wt1, hh, DIM, b1, nullptr);
    // 3) LayerNorm + GELU (fp16 in/out)
    ln_gelu_h_kernel<<<NROWS, 256>>>(hh, gamma, beta, act);
    // 4) enc = gelu(ln(h)) @ W2 + b2  (fp16 out, fused ||row||^2 partials)
    gemm_enc<<<dim3(DIM / 128, NROWS / 128), 128, GEMM_SMEM>>>(
        act, wt2, eh, DIM, b2, nsum);
    // 5) sim lower-tri fp16 1-pass; normalization + mirror + dup fused
    const int NT = NROWS / 128;
    sim_tc_kernel<<<NT * (NT + 1) / 2, 128, SIM_SMEM>>>(eh, nsum, out, dup);
}

// round 16
// speedup vs baseline: 1.0716x; 1.0155x over previous
#include <cuda_runtime.h>
#include <cuda_bf16.h>
#include <cuda_fp16.h>
#include <math.h>
#include <stdint.h>

#define NROWS 8192
#define DIM   1024
#define THR   0.85f

// Scratch (allocation-free: __device__ globals)
__device__ float g_h[(size_t)NROWS * DIM];              // 32 MB: h-fp16 | enc-fp16
__device__ __nv_bfloat16 g_hi[(size_t)NROWS * DIM];     // 16 MB (act fp16)
__device__ __nv_bfloat16 g_wt[(size_t)2 * DIM * DIM];   // 4 MB (Wt1, Wt2 fp16)
__device__ float g_partial[8 * NROWS];                  // 256 KB (per-colblock ||.||^2)

// ===========================================================================
// sm_80-generic PTX helpers (base sm_103 target: no tcgen05)
// ===========================================================================
__device__ __forceinline__ uint32_t smem_u32(const void* p) {
    uint32_t a;
    asm("{ .reg .u64 t; cvta.to.shared.u64 t, %1; cvt.u32.u64 %0, t; }"
        : "=r"(a) : "l"(p));
    return a;
}
__device__ __forceinline__ void cp16(uint32_t dst, const void* src) {
    asm volatile("cp.async.cg.shared.global [%0], [%1], 16;"
                 :: "r"(dst), "l"(src));
}
__device__ __forceinline__ void ldsm_x4(uint32_t* r, uint32_t addr) {
    asm volatile("ldmatrix.sync.aligned.m8n8.x4.shared.b16 {%0,%1,%2,%3}, [%4];"
                 : "=r"(r[0]), "=r"(r[1]), "=r"(r[2]), "=r"(r[3]) : "r"(addr));
}
__device__ __forceinline__ void mma_f16(float* c, const uint32_t* a,
                                        const uint32_t* b) {
    asm volatile("mma.sync.aligned.m16n8k16.row.col.f32.f16.f16.f32 "
                 "{%0,%1,%2,%3}, {%4,%5,%6,%7}, {%8,%9}, {%0,%1,%2,%3};"
                 : "+f"(c[0]), "+f"(c[1]), "+f"(c[2]), "+f"(c[3])
                 : "r"(a[0]), "r"(a[1]), "r"(a[2]), "r"(a[3]),
                   "r"(b[0]), "r"(b[1]));
}
__device__ __forceinline__ void stcs2(float* p, float x, float y) {
    asm volatile("st.global.cs.v2.f32 [%0], {%1, %2};"
                 :: "l"(p), "f"(x), "f"(y) : "memory");
}
__device__ __forceinline__ void stcs1(float* p, float x) {
    asm volatile("st.global.cs.f32 [%0], %1;" :: "l"(p), "f"(x) : "memory");
}

// smem tile: 128 rows x 64B. 16B-chunk swizzle, conflict-free LDSM phases.
__device__ __forceinline__ uint32_t swz(uint32_t row, uint32_t chunk) {
    uint32_t c = chunk ^ (row & 3u) ^ ((row >> 2) & 1u);
    return row * 64u + c * 16u;
}

// Load one phase of fragments (A 64 rows, B 64 cols) from a stage.
#define LOAD_FRAGS(A, B, uA_, uB_, ksoff)                                   \
    do {                                                                    \
        _Pragma("unroll")                                                   \
        for (int mt = 0; mt < 4; mt++)                                      \
            ldsm_x4((A)[mt], (uA_) + swz(arow0 + mt * 16, (ksoff) + achb)); \
        _Pragma("unroll")                                                   \
        for (int p = 0; p < 4; p++) {                                       \
            uint32_t r_[4];                                                 \
            ldsm_x4(r_, (uB_) + swz(brow0 + p * 16, (ksoff) + bchb));       \
            (B)[p * 2][0] = r_[0]; (B)[p * 2][1] = r_[1];                   \
            (B)[p * 2 + 1][0] = r_[2]; (B)[p * 2 + 1][1] = r_[3];           \
        }                                                                   \
    } while (0)

#define MMA_ALL(A, B)                                                       \
    do {                                                                    \
        _Pragma("unroll")                                                   \
        for (int mt = 0; mt < 4; mt++)                                      \
            _Pragma("unroll")                                               \
            for (int nt = 0; nt < 8; nt++)                                  \
                mma_f16(acc[mt][nt], (A)[mt], (B)[nt]);                     \
    } while (0)

// Round-12 proven mainloop: BK=32, 4 stages, reg-double-buffered frags.
#define GEMM_MAINLOOP()                                                     \
    load_stage(0, 0);                                                       \
    asm volatile("cp.async.commit_group;");                                 \
    load_stage(1, 1);                                                       \
    asm volatile("cp.async.commit_group;");                                 \
    load_stage(2, 2);                                                       \
    asm volatile("cp.async.commit_group;");                                 \
    asm volatile("cp.async.wait_group 1;");                                 \
    __syncthreads();                                                        \
    LOAD_FRAGS(a0, b0, sb, sb + 8192u, 0u);                                 \
    int st = 0;                                                             \
    for (int kc = 0; kc < 32; kc++) {                                       \
        const uint32_t uA = sb + st * 16384u;                               \
        const uint32_t uB = uA + 8192u;                                     \
        LOAD_FRAGS(a1, b1, uA, uB, 2u);                                     \
        MMA_ALL(a0, b0);                                                    \
        if (kc + 1 < 32) {                                                  \
            const uint32_t uA2 = sb + ((st + 1) & 3) * 16384u;              \
            LOAD_FRAGS(a0, b0, uA2, uA2 + 8192u, 0u);                       \
        }                                                                   \
        if (kc + 3 < 32) load_stage((st + 3) & 3, kc + 3);                  \
        asm volatile("cp.async.commit_group;");                             \
        MMA_ALL(a1, b1);                                                    \
        asm volatile("cp.async.wait_group 1;");                             \
        __syncthreads();                                                    \
        st = (st + 1) & 3;                                                  \
    }

// ===========================================================================
// Encoder GEMM: fp16 1-pass, 128x128 tile, 4 warps (64x64 warp tile),
// 4-stage cp.async, reg-double-buffered fragments. If nsum != nullptr,
// epilogue accumulates per-row sum-of-squares of fp16-rounded outputs into
// nsum[blockIdx.x * NROWS + r] (2 atomic contributors -> deterministic).
// ===========================================================================
__global__ __launch_bounds__(128, 2) void gemm_enc(
    const __half* __restrict__ A, const __half* __restrict__ B,
    __half* __restrict__ C, int ldc, const float* __restrict__ bias,
    float* __restrict__ nsum) {
    extern __shared__ char sm[];
    const uint32_t sb = smem_u32(sm);

    const int rowBase = blockIdx.y * 128;
    const int colBase = blockIdx.x * 128;

    const int tid = threadIdx.x;
    const int wid = tid >> 5;
    const int lane = tid & 31;
    const int wm = (wid & 1) * 64;
    const int wn = (wid >> 1) * 64;

    const char* gA = (const char*)A + (size_t)rowBase * 2048;
    const char* gB = (const char*)B + (size_t)colBase * 2048;

    auto load_stage = [&](int st_, int kc_) {
        const char* bases[2] = {gA, gB};
#pragma unroll
        for (int t = 0; t < 2; t++) {
#pragma unroll
            for (int h = 0; h < 4; h++) {
                const int c = tid + h * 128;
                const uint32_t row = c >> 2, kch = c & 3;
                const uint32_t dst = sb + st_ * 16384u + t * 8192u + swz(row, kch);
                cp16(dst, bases[t] + (size_t)row * 2048 + (size_t)kc_ * 64 + kch * 16);
            }
        }
    };

    float acc[4][8][4];
#pragma unroll
    for (int i = 0; i < 4; i++)
#pragma unroll
        for (int j = 0; j < 8; j++)
#pragma unroll
            for (int k = 0; k < 4; k++) acc[i][j][k] = 0.f;

    const uint32_t arow0 = (uint32_t)(wm + (lane & 15));
    const uint32_t achb = (uint32_t)(lane >> 4);
    const uint32_t brow0 = (uint32_t)(wn + (lane & 7) + ((lane & 16) >> 1));
    const uint32_t bchb = (uint32_t)((lane >> 3) & 1);

    uint32_t a0[4][4], b0[8][2], a1[4][4], b1[8][2];

    GEMM_MAINLOOP()

    const int g = lane >> 2, tg = lane & 3;
    float rowsum[4][2];
#pragma unroll
    for (int i = 0; i < 4; i++) { rowsum[i][0] = 0.f; rowsum[i][1] = 0.f; }

#pragma unroll
    for (int mt = 0; mt < 4; mt++)
#pragma unroll
        for (int nt = 0; nt < 8; nt++) {
            const int c0 = colBase + wn + nt * 8 + tg * 2;
            const float bx = bias[c0], by = bias[c0 + 1];
#pragma unroll
            for (int hf = 0; hf < 2; hf++) {
                const int r = rowBase + wm + mt * 16 + g + hf * 8;
                const float vx = acc[mt][nt][hf * 2 + 0] + bx;
                const float vy = acc[mt][nt][hf * 2 + 1] + by;
                __half2 hv;
                hv.x = __float2half(vx); hv.y = __float2half(vy);
                *(__half2*)&C[(size_t)r * ldc + c0] = hv;
                if (nsum) {
                    const float px = __half2float(hv.x);
                    const float py = __half2float(hv.y);
                    rowsum[mt][hf] += px * px + py * py;
                }
            }
        }

    if (nsum) {
#pragma unroll
        for (int mt = 0; mt < 4; mt++)
#pragma unroll
            for (int hf = 0; hf < 2; hf++) {
                float s = rowsum[mt][hf];
                s += __shfl_xor_sync(0xffffffffu, s, 1);
                s += __shfl_xor_sync(0xffffffffu, s, 2);
                if (tg == 0) {
                    const int r = rowBase + wm + mt * 16 + g + hf * 8;
                    atomicAdd(&nsum[blockIdx.x * NROWS + r], s);
                }
            }
    }
}

// ===========================================================================
// Sim GEMM: fp16 1-pass on UNNORMALIZED enc; inv-norm tables built BEFORE the
// mainloop (1 KB smem above pipeline region); epilogue scales acc, direct
// streaming store (+dup), then smem-staged transposed mirror (streaming).
// ===========================================================================
__global__ __launch_bounds__(128, 2) void sim_tc_kernel(
    const __half* __restrict__ E, const float* __restrict__ nsum,
    float* __restrict__ out, float* __restrict__ dup) {
    extern __shared__ char sm[];
    const uint32_t sb = smem_u32(sm);

    const int b = blockIdx.x;
    int bi = (int)((sqrtf(8.f * b + 1.f) - 1.f) * 0.5f);
    while ((bi + 1) * (bi + 2) / 2 <= b) bi++;
    while (bi * (bi + 1) / 2 > b) bi--;
    const int bj = b - bi * (bi + 1) / 2;
    const int rowBase = bi * 128;
    const int colBase = bj * 128;
    const bool diag = (rowBase == colBase);

    const int tid = threadIdx.x;
    const int wid = tid >> 5;
    const int lane = tid & 31;
    const int wm = (wid & 1) * 64;
    const int wn = (wid >> 1) * 64;

    // ---- build inv-norm tables up front (region above pipeline smem) ----
    float* rns = (float*)(sm + 66048);   // [128]
    float* cns = rns + 128;              // [128]
    {
        float s = 0.f;
#pragma unroll
        for (int p = 0; p < 8; p++) s += nsum[p * NROWS + rowBase + tid];
        rns[tid] = rsqrtf(fmaxf(s, 1e-24f));
        float s2 = 0.f;
#pragma unroll
        for (int p = 0; p < 8; p++) s2 += nsum[p * NROWS + colBase + tid];
        cns[tid] = rsqrtf(fmaxf(s2, 1e-24f));
    }
    // (ordered before post-loop reads by the mainloop's __syncthreads)

    const char* gA = (const char*)E + (size_t)rowBase * 2048;
    const char* gB = (const char*)E + (size_t)colBase * 2048;

    auto load_stage = [&](int st_, int kc_) {
        const char* bases[2] = {gA, gB};
#pragma unroll
        for (int t = 0; t < 2; t++) {
#pragma unroll
            for (int h = 0; h < 4; h++) {
                const int c = tid + h * 128;
                const uint32_t row = c >> 2, kch = c & 3;
                const uint32_t dst = sb + st_ * 16384u + t * 8192u + swz(row, kch);
                cp16(dst, bases[t] + (size_t)row * 2048 + (size_t)kc_ * 64 + kch * 16);
            }
        }
    };

    float acc[4][8][4];
#pragma unroll
    for (int i = 0; i < 4; i++)
#pragma unroll
        for (int j = 0; j < 8; j++)
#pragma unroll
            for (int k = 0; k < 4; k++) acc[i][j][k] = 0.f;

    const uint32_t arow0 = (uint32_t)(wm + (lane & 15));
    const uint32_t achb = (uint32_t)(lane >> 4);
    const uint32_t brow0 = (uint32_t)(wn + (lane & 7) + ((lane & 16) >> 1));
    const uint32_t bchb = (uint32_t)((lane >> 3) & 1);

    uint32_t a0[4][4], b0[8][2], a1[4][4], b1[8][2];

    GEMM_MAINLOOP()

    // ---- scale by invn[r]*invn[c] ----
    const int g = lane >> 2, tg = lane & 3;
    float rn[4][2], cn[8][2];
#pragma unroll
    for (int mt = 0; mt < 4; mt++) {
        rn[mt][0] = rns[wm + mt * 16 + g];
        rn[mt][1] = rns[wm + mt * 16 + g + 8];
    }
#pragma unroll
    for (int nt = 0; nt < 8; nt++) {
        const int cl = wn + nt * 8 + tg * 2;
        cn[nt][0] = cns[cl];
        cn[nt][1] = cns[cl + 1];
    }
#pragma unroll
    for (int mt = 0; mt < 4; mt++)
#pragma unroll
        for (int nt = 0; nt < 8; nt++) {
            acc[mt][nt][0] *= rn[mt][0] * cn[nt][0];
            acc[mt][nt][1] *= rn[mt][0] * cn[nt][1];
            acc[mt][nt][2] *= rn[mt][1] * cn[nt][0];
            acc[mt][nt][3] *= rn[mt][1] * cn[nt][1];
        }

    // ---- epilogue part 1: direct coalesced streaming stores + dup ----
#pragma unroll
    for (int mt = 0; mt < 4; mt++)
#pragma unroll
        for (int nt = 0; nt < 8; nt++) {
            const int c0 = colBase + wn + nt * 8 + tg * 2;
#pragma unroll
            for (int hf = 0; hf < 2; hf++) {
                const int r = rowBase + wm + mt * 16 + g + hf * 8;
                const float vx = acc[mt][nt][hf * 2 + 0];
                const float vy = acc[mt][nt][hf * 2 + 1];
                if (!diag) {
                    stcs2(&out[(size_t)r * NROWS + c0], vx, vy);
                    if (dup) {
                        if (vx > THR) dup[r] = 1.0f;
                        if (vy > THR) dup[r] = 1.0f;
                    }
                } else {
                    if (r >= c0) {
                        stcs1(&out[(size_t)r * NROWS + c0], vx);
                        if (dup && r > c0 && vx > THR) dup[r] = 1.0f;
                    }
                    if (r >= c0 + 1) {
                        stcs1(&out[(size_t)r * NROWS + c0 + 1], vy);
                        if (dup && r > c0 + 1 && vy > THR) dup[r] = 1.0f;
                    }
                }
            }
        }

    // ---- epilogue part 2: smem-staged transposed mirror (streaming) ----
    asm volatile("cp.async.wait_group 0;");
    __syncthreads();
    float* tile = (float*)sm;  // [128][129]
#pragma unroll
    for (int mt = 0; mt < 4; mt++)
#pragma unroll
        for (int nt = 0; nt < 8; nt++) {
            const int cl = wn + nt * 8 + tg * 2;
#pragma unroll
            for (int hf = 0; hf < 2; hf++) {
                const int rl = wm + mt * 16 + g + hf * 8;
                tile[rl * 129 + cl] = acc[mt][nt][hf * 2 + 0];
                tile[rl * 129 + cl + 1] = acc[mt][nt][hf * 2 + 1];
            }
        }
    __syncthreads();
    for (int it = tid; it < 16384; it += 128) {
        const int c = it >> 7, r = it & 127;
        if (!diag || r > c)
            stcs1(&out[(size_t)(colBase + c) * NROWS + rowBase + r],
                  tile[r * 129 + c]);
    }
}

// ===========================================================================
// prep: split S -> fp16 (8192 blocks); transpose+convert W1/W2 (2048);
// zero nsum partials (64); zero dup (8).
// ===========================================================================
__global__ __launch_bounds__(256) void prep_kernel(
    const float* __restrict__ S, const float* __restrict__ W1,
    const float* __restrict__ W2, __half* __restrict__ act,
    __half* __restrict__ wt1, __half* __restrict__ wt2,
    float* __restrict__ nsum, float* __restrict__ dup) {
    const int b = blockIdx.x;
    const int tid = threadIdx.x;
    if (b < 8192) {
        const size_t i = (size_t)b * 256 + tid;
        float4 x = ((const float4*)S)[i];
        __half2 hp0, hp1;
        hp0.x = __float2half(x.x); hp0.y = __float2half(x.y);
        hp1.x = __float2half(x.z); hp1.y = __float2half(x.w);
        uint2 hv;
        hv.x = *(uint32_t*)&hp0; hv.y = *(uint32_t*)&hp1;
        ((uint2*)act)[i] = hv;
    } else if (b < 8192 + 2048) {
        const int b2 = b - 8192;
        const float* W = (b2 < 1024) ? W1 : W2;
        __half* Wt = (b2 < 1024) ? wt1 : wt2;
        const int b3 = b2 & 1023;
        const int n0 = (b3 & 31) * 32, k0 = (b3 >> 5) * 32;
        __shared__ float t[32][33];
        const int x = tid & 31, ty = tid >> 5;
#pragma unroll
        for (int yy = ty; yy < 32; yy += 8)
            t[yy][x] = W[(size_t)(k0 + yy) * DIM + n0 + x];
        __syncthreads();
#pragma unroll
        for (int yy = ty; yy < 32; yy += 8)
            Wt[(size_t)(n0 + yy) * DIM + k0 + x] = __float2half(t[x][yy]);
    } else if (b < 8192 + 2048 + 64) {
        const int b4 = b - (8192 + 2048);
        float4 z; z.x = 0.f; z.y = 0.f; z.z = 0.f; z.w = 0.f;
        ((float4*)nsum)[(size_t)b4 * 256 + tid] = z;
    } else {
        if (dup) {
            const int b5 = b - (8192 + 2048 + 64);
            float4 z; z.x = 0.f; z.y = 0.f; z.z = 0.f; z.w = 0.f;
            ((float4*)dup)[(size_t)b5 * 256 + tid] = z;
        }
    }
}

// ===========================================================================
// LayerNorm + exact GELU: fp16 in (h), fp16 out
// ===========================================================================
__global__ __launch_bounds__(256) void ln_gelu_h_kernel(
    const __half* __restrict__ h, const float* __restrict__ gamma,
    const float* __restrict__ beta, __half* __restrict__ hi) {
    const int row = blockIdx.x;
    const int t = threadIdx.x;

    uint2 raw = ((const uint2*)(h + (size_t)row * DIM))[t];
    __half2 p0 = *(__half2*)&raw.x;
    __half2 p1 = *(__half2*)&raw.y;
    float x0 = __half2float(p0.x), x1 = __half2float(p0.y);
    float x2 = __half2float(p1.x), x3 = __half2float(p1.y);

    float s1 = x0 + x1 + x2 + x3;
    float s2 = x0 * x0 + x1 * x1 + x2 * x2 + x3 * x3;
#pragma unroll
    for (int o = 16; o > 0; o >>= 1) {
        s1 += __shfl_xor_sync(0xffffffffu, s1, o);
        s2 += __shfl_xor_sync(0xffffffffu, s2, o);
    }
    __shared__ float r1[8], r2[8];
    if ((t & 31) == 0) { r1[t >> 5] = s1; r2[t >> 5] = s2; }
    __syncthreads();
    if (t < 32) {
        s1 = (t < 8) ? r1[t] : 0.f;
        s2 = (t < 8) ? r2[t] : 0.f;
#pragma unroll
        for (int o = 4; o > 0; o >>= 1) {
            s1 += __shfl_xor_sync(0xffffffffu, s1, o);
            s2 += __shfl_xor_sync(0xffffffffu, s2, o);
        }
        if (t == 0) { r1[0] = s1; r2[0] = s2; }
    }
    __syncthreads();
    const float mu = r1[0] * (1.f / DIM);
    const float var = r2[0] * (1.f / DIM) - mu * mu;
    const float rstd = rsqrtf(var + 1e-5f);

    const float4 g = *(const float4*)&gamma[t * 4];
    const float4 bb = *(const float4*)&beta[t * 4];
    float y[4] = { (x0 - mu) * rstd * g.x + bb.x,
                   (x1 - mu) * rstd * g.y + bb.y,
                   (x2 - mu) * rstd * g.z + bb.z,
                   (x3 - mu) * rstd * g.w + bb.w };
    float v[4];
#pragma unroll
    for (int i = 0; i < 4; i++)
        v[i] = 0.5f * y[i] * (1.f + erff(y[i] * 0.70710678118654752f));

    __half2 hp0, hp1;
    hp0.x = __float2half(v[0]); hp0.y = __float2half(v[1]);
    hp1.x = __float2half(v[2]); hp1.y = __float2half(v[3]);
    uint2 hv;
    hv.x = *(uint32_t*)&hp0; hv.y = *(uint32_t*)&hp1;
    ((uint2*)hi)[(size_t)row * (DIM / 4) + t] = hv;
}

// ===========================================================================
extern "C" void kernel_launch(void* const* d_in, const int* in_sizes, int n_in,
                              void* d_out, int out_size) {
    const float* S     = (const float*)d_in[0];
    const float* W1    = (const float*)d_in[1];
    const float* b1    = (const float*)d_in[2];
    const float* gamma = (const float*)d_in[3];
    const float* beta  = (const float*)d_in[4];
    const float* W2    = (const float*)d_in[5];
    const float* b2    = (const float*)d_in[6];
    float* out = (float*)d_out;

    float* hbuf;
    __nv_bfloat16 *hib, *wtb;
    float* nsum;
    cudaGetSymbolAddress((void**)&hbuf, g_h);
    cudaGetSymbolAddress((void**)&hib, g_hi);
    cudaGetSymbolAddress((void**)&wtb, g_wt);
    cudaGetSymbolAddress((void**)&nsum, g_partial);
    __half* act = (__half*)hib;
    __half* wt1 = (__half*)wtb;
    __half* wt2 = wt1 + (size_t)DIM * DIM;
    __half* hh  = (__half*)hbuf;
    __half* eh  = hh + (size_t)NROWS * DIM;

    const int GEMM_SMEM = 4 * 16384;           // 64 KB
    const int SIM_SMEM = 128 * 129 * 4 + 1024; // 67072 B (pipeline + tables)
    cudaFuncSetAttribute(gemm_enc,
                         cudaFuncAttributeMaxDynamicSharedMemorySize, GEMM_SMEM);
    cudaFuncSetAttribute(sim_tc_kernel,
                         cudaFuncAttributeMaxDynamicSharedMemorySize, SIM_SMEM);

    float* dup = nullptr;
    if (out_size >= NROWS * NROWS + NROWS) dup = out + (size_t)NROWS * NROWS;

    // 1) prep: S -> fp16; W1, W2 -> Wt fp16; zero nsum + dup (single launch)
    prep_kernel<<<8192 + 2048 + 64 + 8, 256>>>(S, W1, W2, act, wt1, wt2,
                                               nsum, dup);
    // 2) h = S @ W1 + b1  (fp16 1-pass, fp16 output)
    gemm_enc<<<dim3(DIM / 128, NROWS / 128), 128, GEMM_SMEM>>>(
        act, wt1, hh, DIM, b1, nullptr);
    // 3) LayerNorm + GELU (fp16 in/out)
    ln_gelu_h_kernel<<<NROWS, 256>>>(hh, gamma, beta, act);
    // 4) enc = gelu(ln(h)) @ W2 + b2  (fp16 out, fused ||row||^2 partials)
    gemm_enc<<<dim3(DIM / 128, NROWS / 128), 128, GEMM_SMEM>>>(
        act, wt2, eh, DIM, b2, nsum);
    // 5) sim lower-tri fp16 1-pass; normalization + mirror + dup fused
    const int NT = NROWS / 128;
    sim_tc_kernel<<<NT * (NT + 1) / 2, 128, SIM_SMEM>>>(eh, nsum, out, dup);
}

// round 17
// speedup vs baseline: 1.0739x; 1.0022x over previous
#include <cuda_runtime.h>
#include <cuda_bf16.h>
#include <cuda_fp16.h>
#include <math.h>
#include <stdint.h>

#define NROWS 8192
#define DIM   1024
#define THR   0.85f

// Scratch (allocation-free: __device__ globals)
__device__ float g_h[(size_t)NROWS * DIM];              // 32 MB: h-fp16 | enc-fp16
__device__ __nv_bfloat16 g_hi[(size_t)NROWS * DIM];     // 16 MB (act fp16)
__device__ __nv_bfloat16 g_wt[(size_t)2 * DIM * DIM];   // 4 MB (Wt1, Wt2 fp16)
__device__ float g_partial[8 * NROWS];                  // 256 KB (per-colblock ||.||^2)

// ===========================================================================
// sm_80-generic PTX helpers (base sm_103 target: no tcgen05)
// ===========================================================================
__device__ __forceinline__ uint32_t smem_u32(const void* p) {
    uint32_t a;
    asm("{ .reg .u64 t; cvta.to.shared.u64 t, %1; cvt.u32.u64 %0, t; }"
        : "=r"(a) : "l"(p));
    return a;
}
__device__ __forceinline__ void cp16(uint32_t dst, const void* src) {
    asm volatile("cp.async.cg.shared.global [%0], [%1], 16;"
                 :: "r"(dst), "l"(src));
}
__device__ __forceinline__ void ldsm_x4(uint32_t* r, uint32_t addr) {
    asm volatile("ldmatrix.sync.aligned.m8n8.x4.shared.b16 {%0,%1,%2,%3}, [%4];"
                 : "=r"(r[0]), "=r"(r[1]), "=r"(r[2]), "=r"(r[3]) : "r"(addr));
}
__device__ __forceinline__ void mma_f16(float* c, const uint32_t* a,
                                        const uint32_t* b) {
    asm volatile("mma.sync.aligned.m16n8k16.row.col.f32.f16.f16.f32 "
                 "{%0,%1,%2,%3}, {%4,%5,%6,%7}, {%8,%9}, {%0,%1,%2,%3};"
                 : "+f"(c[0]), "+f"(c[1]), "+f"(c[2]), "+f"(c[3])
                 : "r"(a[0]), "r"(a[1]), "r"(a[2]), "r"(a[3]),
                   "r"(b[0]), "r"(b[1]));
}
__device__ __forceinline__ void stcs2(float* p, float x, float y) {
    asm volatile("st.global.cs.v2.f32 [%0], {%1, %2};"
                 :: "l"(p), "f"(x), "f"(y) : "memory");
}
__device__ __forceinline__ void stcs1(float* p, float x) {
    asm volatile("st.global.cs.f32 [%0], %1;" :: "l"(p), "f"(x) : "memory");
}

// smem tile: 128 rows x 64B. 16B-chunk swizzle, conflict-free LDSM phases.
__device__ __forceinline__ uint32_t swz(uint32_t row, uint32_t chunk) {
    uint32_t c = chunk ^ (row & 3u) ^ ((row >> 2) & 1u);
    return row * 64u + c * 16u;
}

// Load one phase of fragments (A 64 rows, B 64 cols) from a stage.
#define LOAD_FRAGS(A, B, uA_, uB_, ksoff)                                   \
    do {                                                                    \
        _Pragma("unroll")                                                   \
        for (int mt = 0; mt < 4; mt++)                                      \
            ldsm_x4((A)[mt], (uA_) + swz(arow0 + mt * 16, (ksoff) + achb)); \
        _Pragma("unroll")                                                   \
        for (int p = 0; p < 4; p++) {                                       \
            uint32_t r_[4];                                                 \
            ldsm_x4(r_, (uB_) + swz(brow0 + p * 16, (ksoff) + bchb));       \
            (B)[p * 2][0] = r_[0]; (B)[p * 2][1] = r_[1];                   \
            (B)[p * 2 + 1][0] = r_[2]; (B)[p * 2 + 1][1] = r_[3];           \
        }                                                                   \
    } while (0)

#define MMA_ALL(A, B)                                                       \
    do {                                                                    \
        _Pragma("unroll")                                                   \
        for (int mt = 0; mt < 4; mt++)                                      \
            _Pragma("unroll")                                               \
            for (int nt = 0; nt < 8; nt++)                                  \
                mma_f16(acc[mt][nt], (A)[mt], (B)[nt]);                     \
    } while (0)

// Round-12 proven mainloop: BK=32, 4 stages, reg-double-buffered frags.
// (stage 0 is pre-issued by the caller so norm loads can overlap it)
#define GEMM_MAINLOOP_REST()                                                \
    load_stage(1, 1);                                                       \
    asm volatile("cp.async.commit_group;");                                 \
    load_stage(2, 2);                                                       \
    asm volatile("cp.async.commit_group;");                                 \
    asm volatile("cp.async.wait_group 1;");                                 \
    __syncthreads();                                                        \
    LOAD_FRAGS(a0, b0, sb, sb + 8192u, 0u);                                 \
    int st = 0;                                                             \
    for (int kc = 0; kc < 32; kc++) {                                       \
        const uint32_t uA = sb + st * 16384u;                               \
        const uint32_t uB = uA + 8192u;                                     \
        LOAD_FRAGS(a1, b1, uA, uB, 2u);                                     \
        MMA_ALL(a0, b0);                                                    \
        if (kc + 1 < 32) {                                                  \
            const uint32_t uA2 = sb + ((st + 1) & 3) * 16384u;              \
            LOAD_FRAGS(a0, b0, uA2, uA2 + 8192u, 0u);                       \
        }                                                                   \
        if (kc + 3 < 32) load_stage((st + 3) & 3, kc + 3);                  \
        asm volatile("cp.async.commit_group;");                             \
        MMA_ALL(a1, b1);                                                    \
        asm volatile("cp.async.wait_group 1;");                             \
        __syncthreads();                                                    \
        st = (st + 1) & 3;                                                  \
    }

// ===========================================================================
// Encoder GEMM: fp16 1-pass, 128x128 tile, 4 warps (64x64 warp tile),
// 4-stage cp.async, reg-double-buffered fragments. NSUM (compile-time):
// accumulate per-row sum-of-squares of fp16-rounded outputs into
// nsum[blockIdx.x * NROWS + r] (2 atomic contributors -> deterministic).
// ===========================================================================
template <bool NSUM>
__global__ __launch_bounds__(128, 2) void gemm_enc(
    const __half* __restrict__ A, const __half* __restrict__ B,
    __half* __restrict__ C, int ldc, const float* __restrict__ bias,
    float* __restrict__ nsum) {
    extern __shared__ char sm[];
    const uint32_t sb = smem_u32(sm);

    const int rowBase = blockIdx.y * 128;
    const int colBase = blockIdx.x * 128;

    const int tid = threadIdx.x;
    const int wid = tid >> 5;
    const int lane = tid & 31;
    const int wm = (wid & 1) * 64;
    const int wn = (wid >> 1) * 64;

    const char* gA = (const char*)A + (size_t)rowBase * 2048;
    const char* gB = (const char*)B + (size_t)colBase * 2048;

    auto load_stage = [&](int st_, int kc_) {
        const char* bases[2] = {gA, gB};
#pragma unroll
        for (int t = 0; t < 2; t++) {
#pragma unroll
            for (int h = 0; h < 4; h++) {
                const int c = tid + h * 128;
                const uint32_t row = c >> 2, kch = c & 3;
                const uint32_t dst = sb + st_ * 16384u + t * 8192u + swz(row, kch);
                cp16(dst, bases[t] + (size_t)row * 2048 + (size_t)kc_ * 64 + kch * 16);
            }
        }
    };

    float acc[4][8][4];
#pragma unroll
    for (int i = 0; i < 4; i++)
#pragma unroll
        for (int j = 0; j < 8; j++)
#pragma unroll
            for (int k = 0; k < 4; k++) acc[i][j][k] = 0.f;

    const uint32_t arow0 = (uint32_t)(wm + (lane & 15));
    const uint32_t achb = (uint32_t)(lane >> 4);
    const uint32_t brow0 = (uint32_t)(wn + (lane & 7) + ((lane & 16) >> 1));
    const uint32_t bchb = (uint32_t)((lane >> 3) & 1);

    uint32_t a0[4][4], b0[8][2], a1[4][4], b1[8][2];

    load_stage(0, 0);
    asm volatile("cp.async.commit_group;");
    GEMM_MAINLOOP_REST()

    const int g = lane >> 2, tg = lane & 3;
    float rowsum[4][2];
    if (NSUM) {
#pragma unroll
        for (int i = 0; i < 4; i++) { rowsum[i][0] = 0.f; rowsum[i][1] = 0.f; }
    }

#pragma unroll
    for (int mt = 0; mt < 4; mt++)
#pragma unroll
        for (int nt = 0; nt < 8; nt++) {
            const int c0 = colBase + wn + nt * 8 + tg * 2;
            const float bx = bias[c0], by = bias[c0 + 1];
#pragma unroll
            for (int hf = 0; hf < 2; hf++) {
                const int r = rowBase + wm + mt * 16 + g + hf * 8;
                const float vx = acc[mt][nt][hf * 2 + 0] + bx;
                const float vy = acc[mt][nt][hf * 2 + 1] + by;
                __half2 hv;
                hv.x = __float2half(vx); hv.y = __float2half(vy);
                *(__half2*)&C[(size_t)r * ldc + c0] = hv;
                if (NSUM) {
                    const float px = __half2float(hv.x);
                    const float py = __half2float(hv.y);
                    rowsum[mt][hf] += px * px + py * py;
                }
            }
        }

    if (NSUM) {
#pragma unroll
        for (int mt = 0; mt < 4; mt++)
#pragma unroll
            for (int hf = 0; hf < 2; hf++) {
                float s = rowsum[mt][hf];
                s += __shfl_xor_sync(0xffffffffu, s, 1);
                s += __shfl_xor_sync(0xffffffffu, s, 2);
                if (tg == 0) {
                    const int r = rowBase + wm + mt * 16 + g + hf * 8;
                    atomicAdd(&nsum[blockIdx.x * NROWS + r], s);
                }
            }
    }
}

// ===========================================================================
// Sim GEMM: fp16 1-pass on UNNORMALIZED enc; first stage issued before the
// norm-table build (overlap); epilogue scales acc, direct streaming store
// (+dup), then smem-staged transposed mirror (streaming).
// ===========================================================================
__global__ __launch_bounds__(128, 2) void sim_tc_kernel(
    const __half* __restrict__ E, const float* __restrict__ nsum,
    float* __restrict__ out, float* __restrict__ dup) {
    extern __shared__ char sm[];
    const uint32_t sb = smem_u32(sm);

    // direct lower-tri index: b = bi*(bi+1)/2 + bj
    const int b = blockIdx.x;
    int bi = (int)((sqrtf(8.f * (float)b + 1.f) - 1.f) * 0.5f);
    // single monotone correction (float sqrt may be off by 1 either way)
    if ((bi + 1) * (bi + 2) / 2 <= b) bi++;
    else if (bi * (bi + 1) / 2 > b) bi--;
    const int bj = b - bi * (bi + 1) / 2;
    const int rowBase = bi * 128;
    const int colBase = bj * 128;
    const bool diag = (bi == bj);

    const int tid = threadIdx.x;
    const int wid = tid >> 5;
    const int lane = tid & 31;
    const int wm = (wid & 1) * 64;
    const int wn = (wid >> 1) * 64;

    const char* gA = (const char*)E + (size_t)rowBase * 2048;
    const char* gB = (const char*)E + (size_t)colBase * 2048;

    auto load_stage = [&](int st_, int kc_) {
        const char* bases[2] = {gA, gB};
#pragma unroll
        for (int t = 0; t < 2; t++) {
#pragma unroll
            for (int h = 0; h < 4; h++) {
                const int c = tid + h * 128;
                const uint32_t row = c >> 2, kch = c & 3;
                const uint32_t dst = sb + st_ * 16384u + t * 8192u + swz(row, kch);
                cp16(dst, bases[t] + (size_t)row * 2048 + (size_t)kc_ * 64 + kch * 16);
            }
        }
    };

    // issue stage 0 FIRST, then build inv-norm tables under it
    load_stage(0, 0);
    asm volatile("cp.async.commit_group;");

    float* rns = (float*)(sm + 66048);   // [128]
    float* cns = rns + 128;              // [128]
    {
        float s = 0.f;
#pragma unroll
        for (int p = 0; p < 8; p++) s += nsum[p * NROWS + rowBase + tid];
        rns[tid] = rsqrtf(fmaxf(s, 1e-24f));
        float s2 = 0.f;
#pragma unroll
        for (int p = 0; p < 8; p++) s2 += nsum[p * NROWS + colBase + tid];
        cns[tid] = rsqrtf(fmaxf(s2, 1e-24f));
    }
    // (ordered before post-loop reads by the mainloop's __syncthreads)

    float acc[4][8][4];
#pragma unroll
    for (int i = 0; i < 4; i++)
#pragma unroll
        for (int j = 0; j < 8; j++)
#pragma unroll
            for (int k = 0; k < 4; k++) acc[i][j][k] = 0.f;

    const uint32_t arow0 = (uint32_t)(wm + (lane & 15));
    const uint32_t achb = (uint32_t)(lane >> 4);
    const uint32_t brow0 = (uint32_t)(wn + (lane & 7) + ((lane & 16) >> 1));
    const uint32_t bchb = (uint32_t)((lane >> 3) & 1);

    uint32_t a0[4][4], b0[8][2], a1[4][4], b1[8][2];

    GEMM_MAINLOOP_REST()

    // ---- scale by invn[r]*invn[c] ----
    const int g = lane >> 2, tg = lane & 3;
    float rn[4][2], cn[8][2];
#pragma unroll
    for (int mt = 0; mt < 4; mt++) {
        rn[mt][0] = rns[wm + mt * 16 + g];
        rn[mt][1] = rns[wm + mt * 16 + g + 8];
    }
#pragma unroll
    for (int nt = 0; nt < 8; nt++) {
        const int cl = wn + nt * 8 + tg * 2;
        cn[nt][0] = cns[cl];
        cn[nt][1] = cns[cl + 1];
    }
#pragma unroll
    for (int mt = 0; mt < 4; mt++)
#pragma unroll
        for (int nt = 0; nt < 8; nt++) {
            acc[mt][nt][0] *= rn[mt][0] * cn[nt][0];
            acc[mt][nt][1] *= rn[mt][0] * cn[nt][1];
            acc[mt][nt][2] *= rn[mt][1] * cn[nt][0];
            acc[mt][nt][3] *= rn[mt][1] * cn[nt][1];
        }

    // ---- epilogue part 1: direct coalesced streaming stores + dup ----
#pragma unroll
    for (int mt = 0; mt < 4; mt++)
#pragma unroll
        for (int nt = 0; nt < 8; nt++) {
            const int c0 = colBase + wn + nt * 8 + tg * 2;
#pragma unroll
            for (int hf = 0; hf < 2; hf++) {
                const int r = rowBase + wm + mt * 16 + g + hf * 8;
                const float vx = acc[mt][nt][hf * 2 + 0];
                const float vy = acc[mt][nt][hf * 2 + 1];
                if (!diag) {
                    stcs2(&out[(size_t)r * NROWS + c0], vx, vy);
                    if (dup) {
                        if (vx > THR) dup[r] = 1.0f;
                        if (vy > THR) dup[r] = 1.0f;
                    }
                } else {
                    if (r >= c0) {
                        stcs1(&out[(size_t)r * NROWS + c0], vx);
                        if (dup && r > c0 && vx > THR) dup[r] = 1.0f;
                    }
                    if (r >= c0 + 1) {
                        stcs1(&out[(size_t)r * NROWS + c0 + 1], vy);
                        if (dup && r > c0 + 1 && vy > THR) dup[r] = 1.0f;
                    }
                }
            }
        }

    // ---- epilogue part 2: smem-staged transposed mirror (streaming) ----
    asm volatile("cp.async.wait_group 0;");
    __syncthreads();
    float* tile = (float*)sm;  // [128][129]
#pragma unroll
    for (int mt = 0; mt < 4; mt++)
#pragma unroll
        for (int nt = 0; nt < 8; nt++) {
            const int cl = wn + nt * 8 + tg * 2;
#pragma unroll
            for (int hf = 0; hf < 2; hf++) {
                const int rl = wm + mt * 16 + g + hf * 8;
                tile[rl * 129 + cl] = acc[mt][nt][hf * 2 + 0];
                tile[rl * 129 + cl + 1] = acc[mt][nt][hf * 2 + 1];
            }
        }
    __syncthreads();
    for (int it = tid; it < 16384; it += 128) {
        const int c = it >> 7, r = it & 127;
        if (!diag || r > c)
            stcs1(&out[(size_t)(colBase + c) * NROWS + rowBase + r],
                  tile[r * 129 + c]);
    }
}

// ===========================================================================
// prep: split S -> fp16 (8192 blocks); transpose+convert W1/W2 (2048);
// zero nsum partials (64); zero dup (8).
// ===========================================================================
__global__ __launch_bounds__(256) void prep_kernel(
    const float* __restrict__ S, const float* __restrict__ W1,
    const float* __restrict__ W2, __half* __restrict__ act,
    __half* __restrict__ wt1, __half* __restrict__ wt2,
    float* __restrict__ nsum, float* __restrict__ dup) {
    const int b = blockIdx.x;
    const int tid = threadIdx.x;
    if (b < 8192) {
        const size_t i = (size_t)b * 256 + tid;
        float4 x = ((const float4*)S)[i];
        __half2 hp0, hp1;
        hp0.x = __float2half(x.x); hp0.y = __float2half(x.y);
        hp1.x = __float2half(x.z); hp1.y = __float2half(x.w);
        uint2 hv;
        hv.x = *(uint32_t*)&hp0; hv.y = *(uint32_t*)&hp1;
        ((uint2*)act)[i] = hv;
    } else if (b < 8192 + 2048) {
        const int b2 = b - 8192;
        const float* W = (b2 < 1024) ? W1 : W2;
        __half* Wt = (b2 < 1024) ? wt1 : wt2;
        const int b3 = b2 & 1023;
        const int n0 = (b3 & 31) * 32, k0 = (b3 >> 5) * 32;
        __shared__ float t[32][33];
        const int x = tid & 31, ty = tid >> 5;
#pragma unroll
        for (int yy = ty; yy < 32; yy += 8)
            t[yy][x] = W[(size_t)(k0 + yy) * DIM + n0 + x];
        __syncthreads();
#pragma unroll
        for (int yy = ty; yy < 32; yy += 8)
            Wt[(size_t)(n0 + yy) * DIM + k0 + x] = __float2half(t[x][yy]);
    } else if (b < 8192 + 2048 + 64) {
        const int b4 = b - (8192 + 2048);
        float4 z; z.x = 0.f; z.y = 0.f; z.z = 0.f; z.w = 0.f;
        ((float4*)nsum)[(size_t)b4 * 256 + tid] = z;
    } else {
        if (dup) {
            const int b5 = b - (8192 + 2048 + 64);
            float4 z; z.x = 0.f; z.y = 0.f; z.z = 0.f; z.w = 0.f;
            ((float4*)dup)[(size_t)b5 * 256 + tid] = z;
        }
    }
}

// ===========================================================================
// LayerNorm + exact GELU: fp16 in (h), fp16 out
// ===========================================================================
__global__ __launch_bounds__(256) void ln_gelu_h_kernel(
    const __half* __restrict__ h, const float* __restrict__ gamma,
    const float* __restrict__ beta, __half* __restrict__ hi) {
    const int row = blockIdx.x;
    const int t = threadIdx.x;

    uint2 raw = ((const uint2*)(h + (size_t)row * DIM))[t];
    __half2 p0 = *(__half2*)&raw.x;
    __half2 p1 = *(__half2*)&raw.y;
    float x0 = __half2float(p0.x), x1 = __half2float(p0.y);
    float x2 = __half2float(p1.x), x3 = __half2float(p1.y);

    float s1 = x0 + x1 + x2 + x3;
    float s2 = x0 * x0 + x1 * x1 + x2 * x2 + x3 * x3;
#pragma unroll
    for (int o = 16; o > 0; o >>= 1) {
        s1 += __shfl_xor_sync(0xffffffffu, s1, o);
        s2 += __shfl_xor_sync(0xffffffffu, s2, o);
    }
    __shared__ float r1[8], r2[8];
    if ((t & 31) == 0) { r1[t >> 5] = s1; r2[t >> 5] = s2; }
    __syncthreads();
    if (t < 32) {
        s1 = (t < 8) ? r1[t] : 0.f;
        s2 = (t < 8) ? r2[t] : 0.f;
#pragma unroll
        for (int o = 4; o > 0; o >>= 1) {
            s1 += __shfl_xor_sync(0xffffffffu, s1, o);
            s2 += __shfl_xor_sync(0xffffffffu, s2, o);
        }
        if (t == 0) { r1[0] = s1; r2[0] = s2; }
    }
    __syncthreads();
    const float mu = r1[0] * (1.f / DIM);
    const float var = r2[0] * (1.f / DIM) - mu * mu;
    const float rstd = rsqrtf(var + 1e-5f);

    const float4 g = *(const float4*)&gamma[t * 4];
    const float4 bb = *(const float4*)&beta[t * 4];
    float y[4] = { (x0 - mu) * rstd * g.x + bb.x,
                   (x1 - mu) * rstd * g.y + bb.y,
                   (x2 - mu) * rstd * g.z + bb.z,
                   (x3 - mu) * rstd * g.w + bb.w };
    float v[4];
#pragma unroll
    for (int i = 0; i < 4; i++)
        v[i] = 0.5f * y[i] * (1.f + erff(y[i] * 0.70710678118654752f));

    __half2 hp0, hp1;
    hp0.x = __float2half(v[0]); hp0.y = __float2half(v[1]);
    hp1.x = __float2half(v[2]); hp1.y = __float2half(v[3]);
    uint2 hv;
    hv.x = *(uint32_t*)&hp0; hv.y = *(uint32_t*)&hp1;
    ((uint2*)hi)[(size_t)row * (DIM / 4) + t] = hv;
}

// ===========================================================================
extern "C" void kernel_launch(void* const* d_in, const int* in_sizes, int n_in,
                              void* d_out, int out_size) {
    const float* S     = (const float*)d_in[0];
    const float* W1    = (const float*)d_in[1];
    const float* b1    = (const float*)d_in[2];
    const float* gamma = (const float*)d_in[3];
    const float* beta  = (const float*)d_in[4];
    const float* W2    = (const float*)d_in[5];
    const float* b2    = (const float*)d_in[6];
    float* out = (float*)d_out;

    float* hbuf;
    __nv_bfloat16 *hib, *wtb;
    float* nsum;
    cudaGetSymbolAddress((void**)&hbuf, g_h);
    cudaGetSymbolAddress((void**)&hib, g_hi);
    cudaGetSymbolAddress((void**)&wtb, g_wt);
    cudaGetSymbolAddress((void**)&nsum, g_partial);
    __half* act = (__half*)hib;
    __half* wt1 = (__half*)wtb;
    __half* wt2 = wt1 + (size_t)DIM * DIM;
    __half* hh  = (__half*)hbuf;
    __half* eh  = hh + (size_t)NROWS * DIM;

    const int GEMM_SMEM = 4 * 16384;           // 64 KB
    const int SIM_SMEM = 128 * 129 * 4 + 1024; // 67072 B (pipeline + tables)
    cudaFuncSetAttribute(gemm_enc<false>,
                         cudaFuncAttributeMaxDynamicSharedMemorySize, GEMM_SMEM);
    cudaFuncSetAttribute(gemm_enc<true>,
                         cudaFuncAttributeMaxDynamicSharedMemorySize, GEMM_SMEM);
    cudaFuncSetAttribute(sim_tc_kernel,
                         cudaFuncAttributeMaxDynamicSharedMemorySize, SIM_SMEM);

    float* dup = nullptr;
    if (out_size >= NROWS * NROWS + NROWS) dup = out + (size_t)NROWS * NROWS;

    // 1) prep: S -> fp16; W1, W2 -> Wt fp16; zero nsum + dup (single launch)
    prep_kernel<<<8192 + 2048 + 64 + 8, 256>>>(S, W1, W2, act, wt1, wt2,
                                               nsum, dup);
    // 2) h = S @ W1 + b1  (fp16 1-pass, fp16 output)
    gemm_enc<false><<<dim3(DIM / 128, NROWS / 128), 128, GEMM_SMEM>>>(
        act, wt1, hh, DIM, b1, nullptr);
    // 3) LayerNorm + GELU (fp16 in/out)
    ln_gelu_h_kernel<<<NROWS, 256>>>(hh, gamma, beta, act);
    // 4) enc = gelu(ln(h)) @ W2 + b2  (fp16 out, fused ||row||^2 partials)
    gemm_enc<true><<<dim3(DIM / 128, NROWS / 128), 128, GEMM_SMEM>>>(
        act, wt2, eh, DIM, b2, nsum);
    // 5) sim lower-tri fp16 1-pass; normalization + mirror + dup fused
    const int NT = NROWS / 128;
    sim_tc_kernel<<<NT * (NT + 1) / 2, 128, SIM_SMEM>>>(eh, nsum, out, dup);
}